// round 14
// baseline (speedup 1.0000x reference)
#include <cuda_runtime.h>
#include <cuda_bf16.h>
#include <cuda_fp16.h>
#include <stdint.h>

#define BATCH 8
#define SEQ   4096
#define CH    64
#define NROWS (BATCH*SEQ)
#define SP    68
#define NSPLIT 4
#define LOG2E 1.4426950408889634f

// ---------------- scratch (__device__ globals; no allocation) --------------
__device__ uint4 g_xi [(size_t)3*NROWS*16];     // pre-split raw Q/K/V, A-layout
__device__ uint4 g_qi [NROWS*16];               // Q_: bf16 hi/lo interleaved rows
__device__ uint4 g_ki [NROWS*16];               // K_: same
__device__ uint4 g_vi [(size_t)BATCH*CH*512];   // V_: fp16 HI only, transposed, swizzled
__device__ uint4 g_wb [3*3072];                 // conv weights, bf16 B-layout
__device__ float g_op [(size_t)NSPLIT*NROWS*CH];
__device__ float g_ls [NSPLIT*NROWS];
__device__ float g_ms [NSPLIT*NROWS];
__device__ float g_bc[3][CH];
__device__ float g_c0[3][CH];
__device__ float g_cL[3][CH];

// ---------------- helpers ---------------------------------------------------
__device__ __forceinline__ uint32_t smem_u32(const void* p) {
    uint32_t a;
    asm("{ .reg .u64 t; cvta.to.shared.u64 t, %1; cvt.u32.u64 %0, t; }"
        : "=r"(a) : "l"(p));
    return a;
}
#define CP16(dst, src)  asm volatile("cp.async.cg.shared.global [%0], [%1], 16;" :: "r"(dst), "l"(src))
#define CP_COMMIT()     asm volatile("cp.async.commit_group;" ::: "memory")
#define CP_WAIT(n)      asm volatile("cp.async.wait_group %0;" :: "n"(n) : "memory")

__device__ __forceinline__ void split2(float x, __nv_bfloat16& h, __nv_bfloat16& l) {
    h = __float2bfloat16_rn(x);
    l = __float2bfloat16_rn(x - __bfloat162float(h));
}
__device__ __forceinline__ uint32_t pack2(__nv_bfloat16 a, __nv_bfloat16 b) {
    __nv_bfloat162 p = __halves2bfloat162(a, b);
    return *reinterpret_cast<uint32_t*>(&p);
}
__device__ __forceinline__ uint32_t pack2h(__half a, __half b) {
    __half2 p = __halves2half2(a, b);
    return *reinterpret_cast<uint32_t*>(&p);
}
__device__ __forceinline__ int wmap(int jp) {
    return (jp >> 3)*16 + (jp & 3)*4 + ((jp >> 2) & 1);
}
__device__ __forceinline__ int wmap_v(int jt) {
    return (jt >> 3)*8 + (jt & 3)*2 + ((jt >> 2) & 1);
}
__device__ __forceinline__ void mma_bf16(float c[4],
                                         uint32_t a0, uint32_t a1, uint32_t a2, uint32_t a3,
                                         uint32_t b0, uint32_t b1)
{
    asm volatile("mma.sync.aligned.m16n8k16.row.col.f32.bf16.bf16.f32 "
                 "{%0,%1,%2,%3}, {%4,%5,%6,%7}, {%8,%9}, {%0,%1,%2,%3};\n"
                 : "+f"(c[0]), "+f"(c[1]), "+f"(c[2]), "+f"(c[3])
                 : "r"(a0), "r"(a1), "r"(a2), "r"(a3), "r"(b0), "r"(b1));
}
__device__ __forceinline__ void mma_f16(float c[4],
                                        uint32_t a0, uint32_t a1, uint32_t a2, uint32_t a3,
                                        uint32_t b0, uint32_t b1)
{
    asm volatile("mma.sync.aligned.m16n8k16.row.col.f32.f16.f16.f32 "
                 "{%0,%1,%2,%3}, {%4,%5,%6,%7}, {%8,%9}, {%0,%1,%2,%3};\n"
                 : "+f"(c[0]), "+f"(c[1]), "+f"(c[2]), "+f"(c[3])
                 : "r"(a0), "r"(a1), "r"(a2), "r"(a3), "r"(b0), "r"(b1));
}

// ---------------------------------------------------------------------------
// compose_all: one launch for all weight/bias prep.
// ---------------------------------------------------------------------------
__global__ __launch_bounds__(256) void compose_all(const float* __restrict__ wq,
                                                   const float* __restrict__ wk,
                                                   const float* __restrict__ wv,
                                                   const float* __restrict__ wd,
                                                   const float* __restrict__ bq,
                                                   const float* __restrict__ bk,
                                                   const float* __restrict__ bv,
                                                   const float* __restrict__ bd,
                                                   uint32_t* __restrict__ wb,
                                                   float* __restrict__ bc,
                                                   float* __restrict__ c0v,
                                                   float* __restrict__ cLv)
{
    const int k = blockIdx.x, chain = blockIdx.y, tid = threadIdx.x;
    const float sgn = (chain == 0) ? LOG2E : 1.f;

    if (k == 3) {
        if (tid < 64) {
            int o = tid;
            const float* b1 = chain == 0 ? bq : (chain == 1 ? bk : bv);
            float s0 = 0.f, s1 = 0.f, s2 = 0.f;
            for (int c = 0; c < CH; c++) {
                float b = b1[c];
                s0 = fmaf(b, wd[0*CH*CH + c*CH + o], s0);
                s1 = fmaf(b, wd[1*CH*CH + c*CH + o], s1);
                s2 = fmaf(b, wd[2*CH*CH + c*CH + o], s2);
            }
            bc [chain*CH + o] = (bd[o] + s0 + s1 + s2)*sgn;
            c0v[chain*CH + o] = s0*sgn;
            cLv[chain*CH + o] = s2*sgn;
        }
        return;
    }

    __shared__ float w1s[CH*CH], wds[CH*CH], wcs[CH*CH];
    const float* w1 = chain == 0 ? wq : (chain == 1 ? wk : wv);
    for (int i = tid; i < CH*CH; i += 256) { w1s[i] = w1[i]; wds[i] = wd[k*CH*CH + i]; }
    __syncthreads();

    {
        int ci = tid >> 2, o0 = (tid & 3) * 16;
        float acc[16] = {};
#pragma unroll 4
        for (int c = 0; c < CH; c++) {
            float a = w1s[ci*CH + c];
#pragma unroll
            for (int j = 0; j < 16; j++) acc[j] = fmaf(a, wds[c*CH + o0 + j], acc[j]);
        }
#pragma unroll
        for (int j = 0; j < 16; j++) wcs[ci*CH + o0 + j] = acc[j]*sgn;
    }
    __syncthreads();

    for (int task = tid; task < 64*32; task += 256) {
        int n = task >> 5, jpl = task & 31;
        float v0 = wcs[(2*jpl)*CH + n];
        float v1 = wcs[(2*jpl + 1)*CH + n];
        __nv_bfloat16 h0, l0, h1, l1;
        split2(v0, h0, l0);
        split2(v1, h1, l1);
        int jp = k*32 + jpl;
        int wx = wmap(jp) ^ ((n & 1) << 4);
        uint32_t* row = wb + (size_t)chain*12288 + n*192;
        row[wx]     = pack2(h0, h1);
        row[wx + 2] = pack2(l0, l1);
    }
}

// ---------------------------------------------------------------------------
// presplit: raw Q/K/V fp32 -> bf16 hi/lo interleaved A-layout rows (+parity)
// ---------------------------------------------------------------------------
__global__ __launch_bounds__(256) void presplit(const float* __restrict__ Q,
                                                const float* __restrict__ K,
                                                const float* __restrict__ V,
                                                uint4* __restrict__ xi)
{
    int gid = blockIdx.x*256 + threadIdx.x;
    int sub = gid & 15;
    int row = gid >> 4;
    int chain = row / NROWS;
    int rowin = row - chain*NROWS;
    const float* X = chain == 0 ? Q : (chain == 1 ? K : V);
    int G = sub >> 2, r = sub & 3;
    int jp0 = G*8 + r, jp1 = jp0 + 4;
    float2 a = *(const float2*)(X + (size_t)rowin*64 + 2*jp0);
    float2 c = *(const float2*)(X + (size_t)rowin*64 + 2*jp1);
    __nv_bfloat16 h0,l0,h1,l1,h2,l2,h3,l3;
    split2(a.x, h0, l0); split2(a.y, h1, l1);
    split2(c.x, h2, l2); split2(c.y, h3, l3);
    uint4 out;
    out.x = pack2(h0, h1);
    out.y = pack2(h2, h3);
    out.z = pack2(l0, l1);
    out.w = pack2(l2, l3);
    int par = (rowin + 1) & 1;
    xi[(size_t)row*16 + ((G ^ par)*4 + r)] = out;
}

// ---------------------------------------------------------------------------
// conv3mma: tensorized composed conv3. M=128/block, 256 threads.
// Weights read via __ldg (L1-resident, 48KB/chain); smem holds only input
// (33KB) -> 3 blocks/SM instead of 2.
// ---------------------------------------------------------------------------
#define CV_SMEM 33280

__global__ __launch_bounds__(256) void conv3mma(const uint4* __restrict__ XI,
                                                const uint4* __restrict__ WB,
                                                const float* __restrict__ BC,
                                                const float* __restrict__ C0,
                                                const float* __restrict__ CL,
                                                uint32_t* __restrict__ qi,
                                                uint32_t* __restrict__ ki,
                                                uint32_t* __restrict__ vi)
{
    extern __shared__ uint32_t sm[];
    uint32_t* In = sm;
    const uint32_t sb = smem_u32(sm);
    const int chain = blockIdx.z;
    const int b = blockIdx.y, m0 = blockIdx.x * 128;
    const int tid = threadIdx.x;

    const uint4* xsrc = XI + (size_t)(chain*NROWS + b*SEQ)*16;
    for (int idx = tid; idx < 130*16; idx += 256) {
        int lr = idx >> 4, q = idx & 15;
        int l = m0 - 1 + lr;
        if (l >= 0 && l < SEQ)
            CP16(sb + lr*256 + q*16, xsrc + (size_t)l*16 + q);
        else
            *(uint4*)(In + lr*64 + q*4) = make_uint4(0,0,0,0);
    }
    CP_COMMIT();
    CP_WAIT(0);
    __syncthreads();

    const int lane = tid & 31, w = tid >> 5;
    const int g = lane >> 2, t = lane & 3;
    const int r0 = w*16 + g;
    const uint4* wbase = WB + (size_t)chain*3072;

    float acc[8][4] = {};

#pragma unroll
    for (int kt = 0; kt < 12; kt++) {
        const int tap = kt >> 2, ktc = kt & 3;
        const int lr0 = r0 + tap, lr1 = lr0 + 8;
        const int wofs = ktc*16 + t*4;
        uint4 A0 = *(const uint4*)(In + lr0*64 + (wofs ^ ((lr0 & 1) << 4)));
        uint4 A1 = *(const uint4*)(In + lr1*64 + (wofs ^ ((lr1 & 1) << 4)));
#pragma unroll
        for (int nt = 0; nt < 8; nt++) {
            const int bn = nt*8 + g;
            uint4 B = __ldg(wbase + bn*48 + (((kt*16 + t*4) ^ ((bn & 1) << 4)) >> 2));
            mma_bf16(acc[nt], A0.x, A1.x, A0.y, A1.y, B.x, B.y);
            mma_bf16(acc[nt], A0.x, A1.x, A0.y, A1.y, B.z, B.w);
            mma_bf16(acc[nt], A0.z, A1.z, A0.w, A1.w, B.x, B.y);
        }
    }

    const float* bcp = BC + chain*CH;
    const float* c0p = C0 + chain*CH;
    const float* cLp = CL + chain*CH;
    const int gr0 = m0 + r0;
    const bool first = (gr0 == 0);
    const bool last  = (gr0 + 8 == SEQ - 1);

    if (chain < 2) {
        uint32_t* out = chain == 0 ? qi : ki;
#pragma unroll
        for (int nt = 0; nt < 8; nt++) {
            int n0 = nt*8 + 2*t, n1 = n0 + 1;
            float v00 = acc[nt][0] + __ldg(bcp + n0);
            float v01 = acc[nt][1] + __ldg(bcp + n1);
            float v10 = acc[nt][2] + __ldg(bcp + n0);
            float v11 = acc[nt][3] + __ldg(bcp + n1);
            if (first) { v00 -= __ldg(c0p + n0); v01 -= __ldg(c0p + n1); }
            if (last)  { v10 -= __ldg(cLp + n0); v11 -= __ldg(cLp + n1); }
            int w0 = wmap(nt*4 + t);
            __nv_bfloat16 h0,l0,h1,l1;
            split2(v00, h0, l0); split2(v01, h1, l1);
            out[((size_t)(b*SEQ + gr0))*64 + w0]     = pack2(h0, h1);
            out[((size_t)(b*SEQ + gr0))*64 + w0 + 2] = pack2(l0, l1);
            split2(v10, h0, l0); split2(v11, h1, l1);
            out[((size_t)(b*SEQ + gr0 + 8))*64 + w0]     = pack2(h0, h1);
            out[((size_t)(b*SEQ + gr0 + 8))*64 + w0 + 2] = pack2(l0, l1);
        }
    } else {
#pragma unroll
        for (int nt = 0; nt < 8; nt++) {
            int n0 = nt*8 + 2*t, n1 = n0 + 1;
            float v00 = acc[nt][0] + __ldg(bcp + n0);
            float v01 = acc[nt][1] + __ldg(bcp + n1);
            float v10 = acc[nt][2] + __ldg(bcp + n0);
            float v11 = acc[nt][3] + __ldg(bcp + n1);
            if (first) { v00 -= __ldg(c0p + n0); v01 -= __ldg(c0p + n1); }
            if (last)  { v10 -= __ldg(cLp + n0); v11 -= __ldg(cLp + n1); }
            float p00 = __shfl_xor_sync(0xffffffffu, v00, 4);
            float p01 = __shfl_xor_sync(0xffffffffu, v01, 4);
            float p10 = __shfl_xor_sync(0xffffffffu, v10, 4);
            float p11 = __shfl_xor_sync(0xffffffffu, v11, 4);
            if ((g & 1) == 0) {
                int kp0 = gr0 >> 1;
                int kp1 = (gr0 + 8) >> 1;
                int w0a = wmap_v(kp0 & 31) ^ ((n0 & 3) << 3);
                int w0b = wmap_v(kp0 & 31) ^ ((n1 & 3) << 3);
                int w1a = wmap_v(kp1 & 31) ^ ((n0 & 3) << 3);
                int w1b = wmap_v(kp1 & 31) ^ ((n1 & 3) << 3);
                size_t t0 = (size_t)(kp0 >> 5)*32, t1 = (size_t)(kp1 >> 5)*32;
                uint32_t* row0 = vi + ((size_t)(b*CH + n0))*2048;
                uint32_t* row1 = vi + ((size_t)(b*CH + n1))*2048;
                row0[t0 + w0a] = pack2h(__float2half_rn(v00), __float2half_rn(p00));
                row1[t0 + w0b] = pack2h(__float2half_rn(v01), __float2half_rn(p01));
                row0[t1 + w1a] = pack2h(__float2half_rn(v10), __float2half_rn(p10));
                row1[t1 + w1b] = pack2h(__float2half_rn(v11), __float2half_rn(p11));
            }
        }
    }
}

// ---------------------------------------------------------------------------
// Flash attention: QK bf16 3-pass (log2 domain), online max with skip-rescale
// vote, P fp16, PV fp16 1-pass vs V-hi. Split-K = 4, single barrier per tile,
// staging after QK, interleaved softmax+PV.
// ---------------------------------------------------------------------------
#define FL_SMEM 49152

__global__ __launch_bounds__(128, 3) void flash_mma11(
    const uint4* __restrict__ qi4, const uint4* __restrict__ ki4,
    const uint4* __restrict__ vi4,
    float* __restrict__ OP, float* __restrict__ LS, float* __restrict__ MS)
{
    extern __shared__ uint32_t sm[];
    const uint32_t sb = smem_u32(sm);
    const int tid = threadIdx.x;
    const int lane = tid & 31, w = tid >> 5;
    const int g = lane >> 2, t = lane & 3;
    const int b = blockIdx.y;
    const int m0 = blockIdx.x * 64;
    const int split = blockIdx.z;
    const int kbase = split * (SEQ/NSPLIT);
    const int NT = SEQ/NSPLIT/64;   // 16

    uint32_t qhF[4][4], qlF[4][4];
    {
        size_t r0 = (size_t)(b*SEQ + m0 + w*16 + g) * 16;
        size_t r1 = r0 + 8*16;
#pragma unroll
        for (int kt = 0; kt < 4; kt++) {
            uint4 a = __ldg(qi4 + r0 + kt*4 + t);
            uint4 c = __ldg(qi4 + r1 + kt*4 + t);
            qhF[kt][0] = a.x; qhF[kt][2] = a.y; qlF[kt][0] = a.z; qlF[kt][2] = a.w;
            qhF[kt][1] = c.x; qhF[kt][3] = c.y; qlF[kt][1] = c.z; qlF[kt][3] = c.w;
        }
    }

    // prefetch tile 0 into buffer 0
    {
        const int n0 = kbase;
#pragma unroll
        for (int rep = 0; rep < 12; rep++) {
            int i = tid + rep*128;
            if (i < 1024) {
                int r = i >> 4, ch = i & 15;
                int chs = ch ^ ((r & 1) << 2);
                CP16(sb + (uint32_t)(r*256 + chs*16),
                     ki4 + (size_t)(b*SEQ + n0 + r)*16 + ch);
            } else {
                int j = i - 1024;
                int row = j >> 3, chunk = j & 7;
                CP16(sb + (uint32_t)(16384 + row*128 + chunk*16),
                     vi4 + (size_t)(b*CH + row)*512 + (n0 >> 6)*8 + chunk);
            }
        }
        CP_COMMIT();
    }

    float oacc[8][4] = {};
    float lsum0 = 0.f, lsum1 = 0.f;
    float mrow0 = -1e30f, mrow1 = -1e30f;

    for (int tt = 0; tt < NT; tt++) {
        CP_WAIT(0);
        __syncthreads();

        const uint32_t* Kt = sm + (size_t)(tt & 1)*6144;
        const uint32_t* Vt = Kt + 4096;
        const int gx = (g & 1) << 4;
        const int gv = (g & 3) << 3;

        // ---- S' = Q K^T (bf16 3-pass, log2-scaled) ----
        float sacc[8][4];
#pragma unroll
        for (int nt = 0; nt < 8; nt++)
#pragma unroll
            for (int c = 0; c < 4; c++) sacc[nt][c] = 0.f;

#pragma unroll
        for (int kt = 0; kt < 4; kt++) {
            const int wofs = (kt*16 + t*4) ^ gx;
#pragma unroll
            for (int nt = 0; nt < 8; nt++) {
                uint4 kf = *(const uint4*)(Kt + (nt*8 + g)*64 + wofs);
                mma_bf16(sacc[nt], qhF[kt][0], qhF[kt][1], qhF[kt][2], qhF[kt][3], kf.x, kf.y);
                mma_bf16(sacc[nt], qhF[kt][0], qhF[kt][1], qhF[kt][2], qhF[kt][3], kf.z, kf.w);
                mma_bf16(sacc[nt], qlF[kt][0], qlF[kt][1], qlF[kt][2], qlF[kt][3], kf.x, kf.y);
            }
        }

        // ---- staging for tile tt+1 (overlaps softmax + PV) ----
        if (tt < NT-1) {
            const int n0 = kbase + (tt + 1)*64;
            const uint32_t kb = sb + (uint32_t)(((tt + 1) & 1) * 24576);
#pragma unroll
            for (int rep = 0; rep < 12; rep++) {
                int i = tid + rep*128;
                if (i < 1024) {
                    int r = i >> 4, ch = i & 15;
                    int chs = ch ^ ((r & 1) << 2);
                    CP16(kb + (uint32_t)(r*256 + chs*16),
                         ki4 + (size_t)(b*SEQ + n0 + r)*16 + ch);
                } else {
                    int j = i - 1024;
                    int row = j >> 3, chunk = j & 7;
                    CP16(kb + (uint32_t)(16384 + row*128 + chunk*16),
                         vi4 + (size_t)(b*CH + row)*512 + (n0 >> 6)*8 + chunk);
                }
            }
            CP_COMMIT();
        }

        // ---- softmax header (skip rescale when no row max changed) ----
        float mt0 = -1e30f, mt1 = -1e30f;
#pragma unroll
        for (int nt = 0; nt < 8; nt++) {
            mt0 = fmaxf(mt0, fmaxf(sacc[nt][0], sacc[nt][1]));
            mt1 = fmaxf(mt1, fmaxf(sacc[nt][2], sacc[nt][3]));
        }
        mt0 = fmaxf(mt0, __shfl_xor_sync(0xffffffffu, mt0, 1));
        mt0 = fmaxf(mt0, __shfl_xor_sync(0xffffffffu, mt0, 2));
        mt1 = fmaxf(mt1, __shfl_xor_sync(0xffffffffu, mt1, 1));
        mt1 = fmaxf(mt1, __shfl_xor_sync(0xffffffffu, mt1, 2));
        float mn0 = fmaxf(mrow0, mt0), mn1 = fmaxf(mrow1, mt1);
        bool up = (mn0 > mrow0) || (mn1 > mrow1);
        if (__any_sync(0xffffffffu, up)) {
            float sc0 = exp2f(mrow0 - mn0), sc1 = exp2f(mrow1 - mn1);
            lsum0 *= sc0; lsum1 *= sc1;
#pragma unroll
            for (int nt = 0; nt < 8; nt++) {
                oacc[nt][0] *= sc0; oacc[nt][1] *= sc0;
                oacc[nt][2] *= sc1; oacc[nt][3] *= sc1;
            }
            mrow0 = mn0; mrow1 = mn1;
        }

        // ---- interleaved exp2/pack + PV HMMAs ----
#pragma unroll
        for (int kt = 0; kt < 4; kt++) {
            const int a = 2*kt, b2 = 2*kt + 1;
            float e00 = exp2f(sacc[a][0]  - mrow0);
            float e01 = exp2f(sacc[a][1]  - mrow0);
            float e02 = exp2f(sacc[a][2]  - mrow1);
            float e03 = exp2f(sacc[a][3]  - mrow1);
            float e10 = exp2f(sacc[b2][0] - mrow0);
            float e11 = exp2f(sacc[b2][1] - mrow0);
            float e12 = exp2f(sacc[b2][2] - mrow1);
            float e13 = exp2f(sacc[b2][3] - mrow1);
            lsum0 += e00 + e01 + e10 + e11;
            lsum1 += e02 + e03 + e12 + e13;
            uint32_t ah0 = pack2h(__float2half_rn(e00), __float2half_rn(e01));
            uint32_t ah1 = pack2h(__float2half_rn(e02), __float2half_rn(e03));
            uint32_t ah2 = pack2h(__float2half_rn(e10), __float2half_rn(e11));
            uint32_t ah3 = pack2h(__float2half_rn(e12), __float2half_rn(e13));
            const int widx = (kt*8 + t*2) ^ gv;
#pragma unroll
            for (int nt = 0; nt < 8; nt++) {
                uint2 vf = *(const uint2*)(Vt + (nt*8 + g)*32 + widx);
                mma_f16(oacc[nt], ah0, ah1, ah2, ah3, vf.x, vf.y);
            }
        }
    }

    lsum0 += __shfl_xor_sync(0xffffffffu, lsum0, 1);
    lsum0 += __shfl_xor_sync(0xffffffffu, lsum0, 2);
    lsum1 += __shfl_xor_sync(0xffffffffu, lsum1, 1);
    lsum1 += __shfl_xor_sync(0xffffffffu, lsum1, 2);

    const size_t row0 = (size_t)(b*SEQ + m0 + w*16 + g);
    const size_t row1 = row0 + 8;
    if (t == 0) {
        LS[(size_t)split*NROWS + row0] = lsum0;
        LS[(size_t)split*NROWS + row1] = lsum1;
        MS[(size_t)split*NROWS + row0] = mrow0;
        MS[(size_t)split*NROWS + row1] = mrow1;
    }

    float* op = OP + (size_t)split*NROWS*CH;
#pragma unroll
    for (int nt = 0; nt < 8; nt++) {
        *(float2*)(op + row0*CH + nt*8 + 2*t) = make_float2(oacc[nt][0], oacc[nt][1]);
        *(float2*)(op + row1*CH + nt*8 + 2*t) = make_float2(oacc[nt][2], oacc[nt][3]);
    }
}

// ---------------------------------------------------------------------------
// Output pointwise conv, 4-way max-aware split-K combine (log2 domain).
// ---------------------------------------------------------------------------
__global__ __launch_bounds__(256) void pw_kernel(const float* __restrict__ OP,
                                                 const float* __restrict__ LS,
                                                 const float* __restrict__ MS,
                                                 const float* __restrict__ W,
                                                 const float* __restrict__ bias,
                                                 float* __restrict__ Y)
{
    __shared__ float Xs[CH*SP];
    __shared__ float Ws[CH*SP];
    __shared__ float as[NSPLIT][64];
    const int  tid  = threadIdx.x;
    const size_t base = (size_t)blockIdx.x * 64;

    if (tid < 64) {
        size_t r = base + tid;
        float m[NSPLIT], M = -1e30f;
#pragma unroll
        for (int s = 0; s < NSPLIT; s++) { m[s] = MS[(size_t)s*NROWS + r]; M = fmaxf(M, m[s]); }
        float wgt[NSPLIT], denom = 0.f;
#pragma unroll
        for (int s = 0; s < NSPLIT; s++) {
            wgt[s] = exp2f(m[s] - M);
            denom = fmaf(LS[(size_t)s*NROWS + r], wgt[s], denom);
        }
        float inv = 1.f / denom;
#pragma unroll
        for (int s = 0; s < NSPLIT; s++) as[s][tid] = wgt[s]*inv;
    }
    __syncthreads();

#pragma unroll
    for (int rep = 0; rep < 4; rep++) {
        int idx = tid + rep*256;
        int r = idx >> 4, q = idx & 15;
        float x0 = 0.f, x1 = 0.f, x2 = 0.f, x3 = 0.f;
#pragma unroll
        for (int s = 0; s < NSPLIT; s++) {
            float a = as[s][r];
            float4 xv = *(const float4*)(OP + (size_t)s*NROWS*CH + (base + r)*CH + q*4);
            x0 = fmaf(xv.x, a, x0);
            x1 = fmaf(xv.y, a, x1);
            x2 = fmaf(xv.z, a, x2);
            x3 = fmaf(xv.w, a, x3);
        }
        Xs[(q*4+0)*SP + r] = x0;
        Xs[(q*4+1)*SP + r] = x1;
        Xs[(q*4+2)*SP + r] = x2;
        Xs[(q*4+3)*SP + r] = x3;
        *(float4*)(Ws + r*SP + q*4) = *(const float4*)(W + idx*4);
    }
    __syncthreads();

    const int tx = tid & 15, ty = tid >> 4;
    const int i0 = ty*4,  c0 = tx*4;
    float acc[4][4] = {};

#pragma unroll 8
    for (int ci = 0; ci < CH; ci++) {
        float4 a4 = *(const float4*)(Xs + ci*SP + i0);
        float4 w4 = *(const float4*)(Ws + ci*SP + c0);
        float a[4] = {a4.x, a4.y, a4.z, a4.w};
        float w[4] = {w4.x, w4.y, w4.z, w4.w};
#pragma unroll
        for (int ii = 0; ii < 4; ii++)
#pragma unroll
            for (int jj = 0; jj < 4; jj++)
                acc[ii][jj] = fmaf(a[ii], w[jj], acc[ii][jj]);
    }

    float4 bv = *(const float4*)(bias + c0);
#pragma unroll
    for (int ii = 0; ii < 4; ii++) {
        float4 o;
        o.x = acc[ii][0] + bv.x;
        o.y = acc[ii][1] + bv.y;
        o.z = acc[ii][2] + bv.z;
        o.w = acc[ii][3] + bv.w;
        *(float4*)(Y + (base + i0 + ii)*CH + c0) = o;
    }
}

// ---------------------------------------------------------------------------
extern "C" void kernel_launch(void* const* d_in, const int* in_sizes, int n_in,
                              void* d_out, int out_size)
{
    const float* Q  = (const float*)d_in[0];
    const float* K  = (const float*)d_in[1];
    const float* V  = (const float*)d_in[2];
    const float* wq = (const float*)d_in[3];
    const float* bq = (const float*)d_in[4];
    const float* wk = (const float*)d_in[5];
    const float* bk = (const float*)d_in[6];
    const float* wv = (const float*)d_in[7];
    const float* bv = (const float*)d_in[8];
    const float* wd = (const float*)d_in[9];
    const float* bd = (const float*)d_in[10];
    const float* wo = (const float*)d_in[11];
    const float* bo = (const float*)d_in[12];
    float* out = (float*)d_out;

    float *op, *ls, *ms, *bc, *c0v, *cLv;
    uint4 *xi, *qi, *ki, *vi, *wb;
    cudaGetSymbolAddress((void**)&op,  g_op);
    cudaGetSymbolAddress((void**)&ls,  g_ls);
    cudaGetSymbolAddress((void**)&ms,  g_ms);
    cudaGetSymbolAddress((void**)&bc,  g_bc);
    cudaGetSymbolAddress((void**)&c0v, g_c0);
    cudaGetSymbolAddress((void**)&cLv, g_cL);
    cudaGetSymbolAddress((void**)&xi,  g_xi);
    cudaGetSymbolAddress((void**)&qi,  g_qi);
    cudaGetSymbolAddress((void**)&ki,  g_ki);
    cudaGetSymbolAddress((void**)&vi,  g_vi);
    cudaGetSymbolAddress((void**)&wb,  g_wb);

    const dim3 gridCA(4, 3);
    const dim3 gridCV(SEQ/128, BATCH, 3);
    const dim3 gridFL(SEQ/64, BATCH, NSPLIT);
    const dim3 gridPW(NROWS/64);

    compose_all<<<gridCA, 256>>>(wq, wk, wv, wd, bq, bk, bv, bd,
                                 (uint32_t*)wb, bc, c0v, cLv);            // 0
    presplit<<<3*NROWS*16/256, 256>>>(Q, K, V, xi);                       // 1

    cudaFuncSetAttribute(conv3mma,
                         cudaFuncAttributeMaxDynamicSharedMemorySize, CV_SMEM);
    conv3mma<<<gridCV, 256, CV_SMEM>>>(xi, wb, bc, c0v, cLv,
                                       (uint32_t*)qi, (uint32_t*)ki,
                                       (uint32_t*)vi);                    // 2

    cudaFuncSetAttribute(flash_mma11,
                         cudaFuncAttributeMaxDynamicSharedMemorySize, FL_SMEM);
    flash_mma11<<<gridFL, 128, FL_SMEM>>>(qi, ki, vi, op, ls, ms);        // 3

    pw_kernel<<<gridPW, 256>>>(op, ls, ms, wo, bo, out);                  // 4
}

// round 15
// speedup vs baseline: 1.0107x; 1.0107x over previous
#include <cuda_runtime.h>
#include <cuda_bf16.h>
#include <cuda_fp16.h>
#include <stdint.h>

#define BATCH 8
#define SEQ   4096
#define CH    64
#define NROWS (BATCH*SEQ)
#define SP    68
#define NSPLIT 4
#define LOG2E 1.4426950408889634f

// ---------------- scratch (__device__ globals; no allocation) --------------
__device__ uint4 g_xi [(size_t)3*NROWS*16];     // pre-split raw Q/K/V, A-layout
__device__ uint4 g_qi [NROWS*16];               // Q_: bf16 hi/lo interleaved rows
__device__ uint4 g_ki [NROWS*16];               // K_: same
__device__ uint4 g_vi [(size_t)BATCH*CH*512];   // V_: fp16 HI only, transposed, swizzled
__device__ uint4 g_wb [3*3072];                 // conv weights, bf16 B-layout
__device__ float g_op [(size_t)NSPLIT*NROWS*CH];
__device__ float g_ls [NSPLIT*NROWS];
__device__ float g_ms [NSPLIT*NROWS];
__device__ float g_bc[3][CH];
__device__ float g_c0[3][CH];
__device__ float g_cL[3][CH];

// ---------------- helpers ---------------------------------------------------
__device__ __forceinline__ uint32_t smem_u32(const void* p) {
    uint32_t a;
    asm("{ .reg .u64 t; cvta.to.shared.u64 t, %1; cvt.u32.u64 %0, t; }"
        : "=r"(a) : "l"(p));
    return a;
}
#define CP16(dst, src)  asm volatile("cp.async.cg.shared.global [%0], [%1], 16;" :: "r"(dst), "l"(src))
#define CP_COMMIT()     asm volatile("cp.async.commit_group;" ::: "memory")
#define CP_WAIT(n)      asm volatile("cp.async.wait_group %0;" :: "n"(n) : "memory")

__device__ __forceinline__ void split2(float x, __nv_bfloat16& h, __nv_bfloat16& l) {
    h = __float2bfloat16_rn(x);
    l = __float2bfloat16_rn(x - __bfloat162float(h));
}
__device__ __forceinline__ uint32_t pack2(__nv_bfloat16 a, __nv_bfloat16 b) {
    __nv_bfloat162 p = __halves2bfloat162(a, b);
    return *reinterpret_cast<uint32_t*>(&p);
}
__device__ __forceinline__ uint32_t pack2h(__half a, __half b) {
    __half2 p = __halves2half2(a, b);
    return *reinterpret_cast<uint32_t*>(&p);
}
__device__ __forceinline__ int wmap(int jp) {
    return (jp >> 3)*16 + (jp & 3)*4 + ((jp >> 2) & 1);
}
__device__ __forceinline__ int wmap_v(int jt) {
    return (jt >> 3)*8 + (jt & 3)*2 + ((jt >> 2) & 1);
}
__device__ __forceinline__ void mma_bf16(float c[4],
                                         uint32_t a0, uint32_t a1, uint32_t a2, uint32_t a3,
                                         uint32_t b0, uint32_t b1)
{
    asm volatile("mma.sync.aligned.m16n8k16.row.col.f32.bf16.bf16.f32 "
                 "{%0,%1,%2,%3}, {%4,%5,%6,%7}, {%8,%9}, {%0,%1,%2,%3};\n"
                 : "+f"(c[0]), "+f"(c[1]), "+f"(c[2]), "+f"(c[3])
                 : "r"(a0), "r"(a1), "r"(a2), "r"(a3), "r"(b0), "r"(b1));
}
__device__ __forceinline__ void mma_f16(float c[4],
                                        uint32_t a0, uint32_t a1, uint32_t a2, uint32_t a3,
                                        uint32_t b0, uint32_t b1)
{
    asm volatile("mma.sync.aligned.m16n8k16.row.col.f32.f16.f16.f32 "
                 "{%0,%1,%2,%3}, {%4,%5,%6,%7}, {%8,%9}, {%0,%1,%2,%3};\n"
                 : "+f"(c[0]), "+f"(c[1]), "+f"(c[2]), "+f"(c[3])
                 : "r"(a0), "r"(a1), "r"(a2), "r"(a3), "r"(b0), "r"(b1));
}

// ---------------------------------------------------------------------------
// compose_all: one launch for all weight/bias prep.
// ---------------------------------------------------------------------------
__global__ __launch_bounds__(256) void compose_all(const float* __restrict__ wq,
                                                   const float* __restrict__ wk,
                                                   const float* __restrict__ wv,
                                                   const float* __restrict__ wd,
                                                   const float* __restrict__ bq,
                                                   const float* __restrict__ bk,
                                                   const float* __restrict__ bv,
                                                   const float* __restrict__ bd,
                                                   uint32_t* __restrict__ wb,
                                                   float* __restrict__ bc,
                                                   float* __restrict__ c0v,
                                                   float* __restrict__ cLv)
{
    const int k = blockIdx.x, chain = blockIdx.y, tid = threadIdx.x;
    const float sgn = (chain == 0) ? LOG2E : 1.f;

    if (k == 3) {
        if (tid < 64) {
            int o = tid;
            const float* b1 = chain == 0 ? bq : (chain == 1 ? bk : bv);
            float s0 = 0.f, s1 = 0.f, s2 = 0.f;
            for (int c = 0; c < CH; c++) {
                float b = b1[c];
                s0 = fmaf(b, wd[0*CH*CH + c*CH + o], s0);
                s1 = fmaf(b, wd[1*CH*CH + c*CH + o], s1);
                s2 = fmaf(b, wd[2*CH*CH + c*CH + o], s2);
            }
            bc [chain*CH + o] = (bd[o] + s0 + s1 + s2)*sgn;
            c0v[chain*CH + o] = s0*sgn;
            cLv[chain*CH + o] = s2*sgn;
        }
        return;
    }

    __shared__ float w1s[CH*CH], wds[CH*CH], wcs[CH*CH];
    const float* w1 = chain == 0 ? wq : (chain == 1 ? wk : wv);
    for (int i = tid; i < CH*CH; i += 256) { w1s[i] = w1[i]; wds[i] = wd[k*CH*CH + i]; }
    __syncthreads();

    {
        int ci = tid >> 2, o0 = (tid & 3) * 16;
        float acc[16] = {};
#pragma unroll 4
        for (int c = 0; c < CH; c++) {
            float a = w1s[ci*CH + c];
#pragma unroll
            for (int j = 0; j < 16; j++) acc[j] = fmaf(a, wds[c*CH + o0 + j], acc[j]);
        }
#pragma unroll
        for (int j = 0; j < 16; j++) wcs[ci*CH + o0 + j] = acc[j]*sgn;
    }
    __syncthreads();

    for (int task = tid; task < 64*32; task += 256) {
        int n = task >> 5, jpl = task & 31;
        float v0 = wcs[(2*jpl)*CH + n];
        float v1 = wcs[(2*jpl + 1)*CH + n];
        __nv_bfloat16 h0, l0, h1, l1;
        split2(v0, h0, l0);
        split2(v1, h1, l1);
        int jp = k*32 + jpl;
        int wx = wmap(jp) ^ ((n & 1) << 4);
        uint32_t* row = wb + (size_t)chain*12288 + n*192;
        row[wx]     = pack2(h0, h1);
        row[wx + 2] = pack2(l0, l1);
    }
}

// ---------------------------------------------------------------------------
// presplit: raw Q/K/V fp32 -> bf16 hi/lo interleaved A-layout rows (+parity)
// ---------------------------------------------------------------------------
__global__ __launch_bounds__(256) void presplit(const float* __restrict__ Q,
                                                const float* __restrict__ K,
                                                const float* __restrict__ V,
                                                uint4* __restrict__ xi)
{
    int gid = blockIdx.x*256 + threadIdx.x;
    int sub = gid & 15;
    int row = gid >> 4;
    int chain = row / NROWS;
    int rowin = row - chain*NROWS;
    const float* X = chain == 0 ? Q : (chain == 1 ? K : V);
    int G = sub >> 2, r = sub & 3;
    int jp0 = G*8 + r, jp1 = jp0 + 4;
    float2 a = *(const float2*)(X + (size_t)rowin*64 + 2*jp0);
    float2 c = *(const float2*)(X + (size_t)rowin*64 + 2*jp1);
    __nv_bfloat16 h0,l0,h1,l1,h2,l2,h3,l3;
    split2(a.x, h0, l0); split2(a.y, h1, l1);
    split2(c.x, h2, l2); split2(c.y, h3, l3);
    uint4 out;
    out.x = pack2(h0, h1);
    out.y = pack2(h2, h3);
    out.z = pack2(l0, l1);
    out.w = pack2(l2, l3);
    int par = (rowin + 1) & 1;
    xi[(size_t)row*16 + ((G ^ par)*4 + r)] = out;
}

// ---------------------------------------------------------------------------
// conv3mma: tensorized composed conv3 (R13 version: smem-staged weights).
// ---------------------------------------------------------------------------
#define CV_SMEM 82432

__global__ __launch_bounds__(256) void conv3mma(const uint4* __restrict__ XI,
                                                const uint4* __restrict__ WB,
                                                const float* __restrict__ BC,
                                                const float* __restrict__ C0,
                                                const float* __restrict__ CL,
                                                uint32_t* __restrict__ qi,
                                                uint32_t* __restrict__ ki,
                                                uint32_t* __restrict__ vi)
{
    extern __shared__ uint32_t sm[];
    uint32_t* In = sm + 12288;
    const uint32_t sb = smem_u32(sm);
    const int chain = blockIdx.z;
    const int b = blockIdx.y, m0 = blockIdx.x * 128;
    const int tid = threadIdx.x;

    const uint4* wbsrc = WB + (size_t)chain*3072;
    for (int i = tid; i < 3072; i += 256) CP16(sb + i*16, wbsrc + i);
    const uint4* xsrc = XI + (size_t)(chain*NROWS + b*SEQ)*16;
    for (int idx = tid; idx < 130*16; idx += 256) {
        int lr = idx >> 4, q = idx & 15;
        int l = m0 - 1 + lr;
        if (l >= 0 && l < SEQ)
            CP16(sb + 49152 + lr*256 + q*16, xsrc + (size_t)l*16 + q);
        else
            *(uint4*)(In + lr*64 + q*4) = make_uint4(0,0,0,0);
    }
    CP_COMMIT();
    CP_WAIT(0);
    __syncthreads();

    const int lane = tid & 31, w = tid >> 5;
    const int g = lane >> 2, t = lane & 3;
    const int r0 = w*16 + g;

    float acc[8][4] = {};

#pragma unroll
    for (int kt = 0; kt < 12; kt++) {
        const int tap = kt >> 2, ktc = kt & 3;
        const int lr0 = r0 + tap, lr1 = lr0 + 8;
        const int wofs = ktc*16 + t*4;
        uint4 A0 = *(const uint4*)(In + lr0*64 + (wofs ^ ((lr0 & 1) << 4)));
        uint4 A1 = *(const uint4*)(In + lr1*64 + (wofs ^ ((lr1 & 1) << 4)));
#pragma unroll
        for (int nt = 0; nt < 8; nt++) {
            const int bn = nt*8 + g;
            uint4 B = *(const uint4*)(sm + bn*192 + ((kt*16 + t*4) ^ ((bn & 1) << 4)));
            mma_bf16(acc[nt], A0.x, A1.x, A0.y, A1.y, B.x, B.y);
            mma_bf16(acc[nt], A0.x, A1.x, A0.y, A1.y, B.z, B.w);
            mma_bf16(acc[nt], A0.z, A1.z, A0.w, A1.w, B.x, B.y);
        }
    }

    const float* bcp = BC + chain*CH;
    const float* c0p = C0 + chain*CH;
    const float* cLp = CL + chain*CH;
    const int gr0 = m0 + r0;
    const bool first = (gr0 == 0);
    const bool last  = (gr0 + 8 == SEQ - 1);

    if (chain < 2) {
        uint32_t* out = chain == 0 ? qi : ki;
#pragma unroll
        for (int nt = 0; nt < 8; nt++) {
            int n0 = nt*8 + 2*t, n1 = n0 + 1;
            float v00 = acc[nt][0] + __ldg(bcp + n0);
            float v01 = acc[nt][1] + __ldg(bcp + n1);
            float v10 = acc[nt][2] + __ldg(bcp + n0);
            float v11 = acc[nt][3] + __ldg(bcp + n1);
            if (first) { v00 -= __ldg(c0p + n0); v01 -= __ldg(c0p + n1); }
            if (last)  { v10 -= __ldg(cLp + n0); v11 -= __ldg(cLp + n1); }
            int w0 = wmap(nt*4 + t);
            __nv_bfloat16 h0,l0,h1,l1;
            split2(v00, h0, l0); split2(v01, h1, l1);
            out[((size_t)(b*SEQ + gr0))*64 + w0]     = pack2(h0, h1);
            out[((size_t)(b*SEQ + gr0))*64 + w0 + 2] = pack2(l0, l1);
            split2(v10, h0, l0); split2(v11, h1, l1);
            out[((size_t)(b*SEQ + gr0 + 8))*64 + w0]     = pack2(h0, h1);
            out[((size_t)(b*SEQ + gr0 + 8))*64 + w0 + 2] = pack2(l0, l1);
        }
    } else {
#pragma unroll
        for (int nt = 0; nt < 8; nt++) {
            int n0 = nt*8 + 2*t, n1 = n0 + 1;
            float v00 = acc[nt][0] + __ldg(bcp + n0);
            float v01 = acc[nt][1] + __ldg(bcp + n1);
            float v10 = acc[nt][2] + __ldg(bcp + n0);
            float v11 = acc[nt][3] + __ldg(bcp + n1);
            if (first) { v00 -= __ldg(c0p + n0); v01 -= __ldg(c0p + n1); }
            if (last)  { v10 -= __ldg(cLp + n0); v11 -= __ldg(cLp + n1); }
            float p00 = __shfl_xor_sync(0xffffffffu, v00, 4);
            float p01 = __shfl_xor_sync(0xffffffffu, v01, 4);
            float p10 = __shfl_xor_sync(0xffffffffu, v10, 4);
            float p11 = __shfl_xor_sync(0xffffffffu, v11, 4);
            if ((g & 1) == 0) {
                int kp0 = gr0 >> 1;
                int kp1 = (gr0 + 8) >> 1;
                int w0a = wmap_v(kp0 & 31) ^ ((n0 & 3) << 3);
                int w0b = wmap_v(kp0 & 31) ^ ((n1 & 3) << 3);
                int w1a = wmap_v(kp1 & 31) ^ ((n0 & 3) << 3);
                int w1b = wmap_v(kp1 & 31) ^ ((n1 & 3) << 3);
                size_t t0 = (size_t)(kp0 >> 5)*32, t1 = (size_t)(kp1 >> 5)*32;
                uint32_t* row0 = vi + ((size_t)(b*CH + n0))*2048;
                uint32_t* row1 = vi + ((size_t)(b*CH + n1))*2048;
                row0[t0 + w0a] = pack2h(__float2half_rn(v00), __float2half_rn(p00));
                row1[t0 + w0b] = pack2h(__float2half_rn(v01), __float2half_rn(p01));
                row0[t1 + w1a] = pack2h(__float2half_rn(v10), __float2half_rn(p10));
                row1[t1 + w1b] = pack2h(__float2half_rn(v11), __float2half_rn(p11));
            }
        }
    }
}

// ---------------------------------------------------------------------------
// Flash attention: QK bf16 3-pass (log2 domain), skip-rescale vote, P fp16,
// PV fp16 1-pass vs V-hi. Split-K = 4. CTA start-phase stagger to break
// co-resident phase lock (softmax windows interleave across CTAs).
// ---------------------------------------------------------------------------
#define FL_SMEM 49152

__global__ __launch_bounds__(128, 3) void flash_mma12(
    const uint4* __restrict__ qi4, const uint4* __restrict__ ki4,
    const uint4* __restrict__ vi4,
    float* __restrict__ OP, float* __restrict__ LS, float* __restrict__ MS)
{
    extern __shared__ uint32_t sm[];
    const uint32_t sb = smem_u32(sm);
    const int tid = threadIdx.x;
    const int lane = tid & 31, w = tid >> 5;
    const int g = lane >> 2, t = lane & 3;
    const int b = blockIdx.y;
    const int m0 = blockIdx.x * 64;
    const int split = blockIdx.z;
    const int kbase = split * (SEQ/NSPLIT);
    const int NT = SEQ/NSPLIT/64;   // 16

    // ---- phase stagger: co-resident CTAs (bid, bid+148, bid+296) get
    //      distinct ~1/3-tile start offsets so softmax windows interleave ----
    {
        int lb = blockIdx.x + 64*(blockIdx.y + 8*blockIdx.z);
        int zph = (lb / 148) % 3;
        if (zph) {
            long long t0 = clock64();
            long long dly = (long long)zph * 1700;
            while (clock64() - t0 < dly) { }
        }
    }

    uint32_t qhF[4][4], qlF[4][4];
    {
        size_t r0 = (size_t)(b*SEQ + m0 + w*16 + g) * 16;
        size_t r1 = r0 + 8*16;
#pragma unroll
        for (int kt = 0; kt < 4; kt++) {
            uint4 a = __ldg(qi4 + r0 + kt*4 + t);
            uint4 c = __ldg(qi4 + r1 + kt*4 + t);
            qhF[kt][0] = a.x; qhF[kt][2] = a.y; qlF[kt][0] = a.z; qlF[kt][2] = a.w;
            qhF[kt][1] = c.x; qhF[kt][3] = c.y; qlF[kt][1] = c.z; qlF[kt][3] = c.w;
        }
    }

    // prefetch tile 0 into buffer 0
    {
        const int n0 = kbase;
#pragma unroll
        for (int rep = 0; rep < 12; rep++) {
            int i = tid + rep*128;
            if (i < 1024) {
                int r = i >> 4, ch = i & 15;
                int chs = ch ^ ((r & 1) << 2);
                CP16(sb + (uint32_t)(r*256 + chs*16),
                     ki4 + (size_t)(b*SEQ + n0 + r)*16 + ch);
            } else {
                int j = i - 1024;
                int row = j >> 3, chunk = j & 7;
                CP16(sb + (uint32_t)(16384 + row*128 + chunk*16),
                     vi4 + (size_t)(b*CH + row)*512 + (n0 >> 6)*8 + chunk);
            }
        }
        CP_COMMIT();
    }

    float oacc[8][4] = {};
    float lsum0 = 0.f, lsum1 = 0.f;
    float mrow0 = -1e30f, mrow1 = -1e30f;

    for (int tt = 0; tt < NT; tt++) {
        CP_WAIT(0);
        __syncthreads();

        const uint32_t* Kt = sm + (size_t)(tt & 1)*6144;
        const uint32_t* Vt = Kt + 4096;
        const int gx = (g & 1) << 4;
        const int gv = (g & 3) << 3;

        // ---- S' = Q K^T (bf16 3-pass, log2-scaled) ----
        float sacc[8][4];
#pragma unroll
        for (int nt = 0; nt < 8; nt++)
#pragma unroll
            for (int c = 0; c < 4; c++) sacc[nt][c] = 0.f;

#pragma unroll
        for (int kt = 0; kt < 4; kt++) {
            const int wofs = (kt*16 + t*4) ^ gx;
#pragma unroll
            for (int nt = 0; nt < 8; nt++) {
                uint4 kf = *(const uint4*)(Kt + (nt*8 + g)*64 + wofs);
                mma_bf16(sacc[nt], qhF[kt][0], qhF[kt][1], qhF[kt][2], qhF[kt][3], kf.x, kf.y);
                mma_bf16(sacc[nt], qhF[kt][0], qhF[kt][1], qhF[kt][2], qhF[kt][3], kf.z, kf.w);
                mma_bf16(sacc[nt], qlF[kt][0], qlF[kt][1], qlF[kt][2], qlF[kt][3], kf.x, kf.y);
            }
        }

        // ---- staging for tile tt+1 (overlaps softmax + PV) ----
        if (tt < NT-1) {
            const int n0 = kbase + (tt + 1)*64;
            const uint32_t kb = sb + (uint32_t)(((tt + 1) & 1) * 24576);
#pragma unroll
            for (int rep = 0; rep < 12; rep++) {
                int i = tid + rep*128;
                if (i < 1024) {
                    int r = i >> 4, ch = i & 15;
                    int chs = ch ^ ((r & 1) << 2);
                    CP16(kb + (uint32_t)(r*256 + chs*16),
                         ki4 + (size_t)(b*SEQ + n0 + r)*16 + ch);
                } else {
                    int j = i - 1024;
                    int row = j >> 3, chunk = j & 7;
                    CP16(kb + (uint32_t)(16384 + row*128 + chunk*16),
                         vi4 + (size_t)(b*CH + row)*512 + (n0 >> 6)*8 + chunk);
                }
            }
            CP_COMMIT();
        }

        // ---- softmax header (skip rescale when no row max changed) ----
        float mt0 = -1e30f, mt1 = -1e30f;
#pragma unroll
        for (int nt = 0; nt < 8; nt++) {
            mt0 = fmaxf(mt0, fmaxf(sacc[nt][0], sacc[nt][1]));
            mt1 = fmaxf(mt1, fmaxf(sacc[nt][2], sacc[nt][3]));
        }
        mt0 = fmaxf(mt0, __shfl_xor_sync(0xffffffffu, mt0, 1));
        mt0 = fmaxf(mt0, __shfl_xor_sync(0xffffffffu, mt0, 2));
        mt1 = fmaxf(mt1, __shfl_xor_sync(0xffffffffu, mt1, 1));
        mt1 = fmaxf(mt1, __shfl_xor_sync(0xffffffffu, mt1, 2));
        float mn0 = fmaxf(mrow0, mt0), mn1 = fmaxf(mrow1, mt1);
        bool up = (mn0 > mrow0) || (mn1 > mrow1);
        if (__any_sync(0xffffffffu, up)) {
            float sc0 = exp2f(mrow0 - mn0), sc1 = exp2f(mrow1 - mn1);
            lsum0 *= sc0; lsum1 *= sc1;
#pragma unroll
            for (int nt = 0; nt < 8; nt++) {
                oacc[nt][0] *= sc0; oacc[nt][1] *= sc0;
                oacc[nt][2] *= sc1; oacc[nt][3] *= sc1;
            }
            mrow0 = mn0; mrow1 = mn1;
        }

        // ---- interleaved exp2/pack + PV HMMAs ----
#pragma unroll
        for (int kt = 0; kt < 4; kt++) {
            const int a = 2*kt, b2 = 2*kt + 1;
            float e00 = exp2f(sacc[a][0]  - mrow0);
            float e01 = exp2f(sacc[a][1]  - mrow0);
            float e02 = exp2f(sacc[a][2]  - mrow1);
            float e03 = exp2f(sacc[a][3]  - mrow1);
            float e10 = exp2f(sacc[b2][0] - mrow0);
            float e11 = exp2f(sacc[b2][1] - mrow0);
            float e12 = exp2f(sacc[b2][2] - mrow1);
            float e13 = exp2f(sacc[b2][3] - mrow1);
            lsum0 += e00 + e01 + e10 + e11;
            lsum1 += e02 + e03 + e12 + e13;
            uint32_t ah0 = pack2h(__float2half_rn(e00), __float2half_rn(e01));
            uint32_t ah1 = pack2h(__float2half_rn(e02), __float2half_rn(e03));
            uint32_t ah2 = pack2h(__float2half_rn(e10), __float2half_rn(e11));
            uint32_t ah3 = pack2h(__float2half_rn(e12), __float2half_rn(e13));
            const int widx = (kt*8 + t*2) ^ gv;
#pragma unroll
            for (int nt = 0; nt < 8; nt++) {
                uint2 vf = *(const uint2*)(Vt + (nt*8 + g)*32 + widx);
                mma_f16(oacc[nt], ah0, ah1, ah2, ah3, vf.x, vf.y);
            }
        }
    }

    lsum0 += __shfl_xor_sync(0xffffffffu, lsum0, 1);
    lsum0 += __shfl_xor_sync(0xffffffffu, lsum0, 2);
    lsum1 += __shfl_xor_sync(0xffffffffu, lsum1, 1);
    lsum1 += __shfl_xor_sync(0xffffffffu, lsum1, 2);

    const size_t row0 = (size_t)(b*SEQ + m0 + w*16 + g);
    const size_t row1 = row0 + 8;
    if (t == 0) {
        LS[(size_t)split*NROWS + row0] = lsum0;
        LS[(size_t)split*NROWS + row1] = lsum1;
        MS[(size_t)split*NROWS + row0] = mrow0;
        MS[(size_t)split*NROWS + row1] = mrow1;
    }

    float* op = OP + (size_t)split*NROWS*CH;
#pragma unroll
    for (int nt = 0; nt < 8; nt++) {
        *(float2*)(op + row0*CH + nt*8 + 2*t) = make_float2(oacc[nt][0], oacc[nt][1]);
        *(float2*)(op + row1*CH + nt*8 + 2*t) = make_float2(oacc[nt][2], oacc[nt][3]);
    }
}

// ---------------------------------------------------------------------------
// Output pointwise conv, 4-way max-aware split-K combine (log2 domain).
// ---------------------------------------------------------------------------
__global__ __launch_bounds__(256) void pw_kernel(const float* __restrict__ OP,
                                                 const float* __restrict__ LS,
                                                 const float* __restrict__ MS,
                                                 const float* __restrict__ W,
                                                 const float* __restrict__ bias,
                                                 float* __restrict__ Y)
{
    __shared__ float Xs[CH*SP];
    __shared__ float Ws[CH*SP];
    __shared__ float as[NSPLIT][64];
    const int  tid  = threadIdx.x;
    const size_t base = (size_t)blockIdx.x * 64;

    if (tid < 64) {
        size_t r = base + tid;
        float m[NSPLIT], M = -1e30f;
#pragma unroll
        for (int s = 0; s < NSPLIT; s++) { m[s] = MS[(size_t)s*NROWS + r]; M = fmaxf(M, m[s]); }
        float wgt[NSPLIT], denom = 0.f;
#pragma unroll
        for (int s = 0; s < NSPLIT; s++) {
            wgt[s] = exp2f(m[s] - M);
            denom = fmaf(LS[(size_t)s*NROWS + r], wgt[s], denom);
        }
        float inv = 1.f / denom;
#pragma unroll
        for (int s = 0; s < NSPLIT; s++) as[s][tid] = wgt[s]*inv;
    }
    __syncthreads();

#pragma unroll
    for (int rep = 0; rep < 4; rep++) {
        int idx = tid + rep*256;
        int r = idx >> 4, q = idx & 15;
        float x0 = 0.f, x1 = 0.f, x2 = 0.f, x3 = 0.f;
#pragma unroll
        for (int s = 0; s < NSPLIT; s++) {
            float a = as[s][r];
            float4 xv = *(const float4*)(OP + (size_t)s*NROWS*CH + (base + r)*CH + q*4);
            x0 = fmaf(xv.x, a, x0);
            x1 = fmaf(xv.y, a, x1);
            x2 = fmaf(xv.z, a, x2);
            x3 = fmaf(xv.w, a, x3);
        }
        Xs[(q*4+0)*SP + r] = x0;
        Xs[(q*4+1)*SP + r] = x1;
        Xs[(q*4+2)*SP + r] = x2;
        Xs[(q*4+3)*SP + r] = x3;
        *(float4*)(Ws + r*SP + q*4) = *(const float4*)(W + idx*4);
    }
    __syncthreads();

    const int tx = tid & 15, ty = tid >> 4;
    const int i0 = ty*4,  c0 = tx*4;
    float acc[4][4] = {};

#pragma unroll 8
    for (int ci = 0; ci < CH; ci++) {
        float4 a4 = *(const float4*)(Xs + ci*SP + i0);
        float4 w4 = *(const float4*)(Ws + ci*SP + c0);
        float a[4] = {a4.x, a4.y, a4.z, a4.w};
        float w[4] = {w4.x, w4.y, w4.z, w4.w};
#pragma unroll
        for (int ii = 0; ii < 4; ii++)
#pragma unroll
            for (int jj = 0; jj < 4; jj++)
                acc[ii][jj] = fmaf(a[ii], w[jj], acc[ii][jj]);
    }

    float4 bv = *(const float4*)(bias + c0);
#pragma unroll
    for (int ii = 0; ii < 4; ii++) {
        float4 o;
        o.x = acc[ii][0] + bv.x;
        o.y = acc[ii][1] + bv.y;
        o.z = acc[ii][2] + bv.z;
        o.w = acc[ii][3] + bv.w;
        *(float4*)(Y + (base + i0 + ii)*CH + c0) = o;
    }
}

// ---------------------------------------------------------------------------
extern "C" void kernel_launch(void* const* d_in, const int* in_sizes, int n_in,
                              void* d_out, int out_size)
{
    const float* Q  = (const float*)d_in[0];
    const float* K  = (const float*)d_in[1];
    const float* V  = (const float*)d_in[2];
    const float* wq = (const float*)d_in[3];
    const float* bq = (const float*)d_in[4];
    const float* wk = (const float*)d_in[5];
    const float* bk = (const float*)d_in[6];
    const float* wv = (const float*)d_in[7];
    const float* bv = (const float*)d_in[8];
    const float* wd = (const float*)d_in[9];
    const float* bd = (const float*)d_in[10];
    const float* wo = (const float*)d_in[11];
    const float* bo = (const float*)d_in[12];
    float* out = (float*)d_out;

    float *op, *ls, *ms, *bc, *c0v, *cLv;
    uint4 *xi, *qi, *ki, *vi, *wb;
    cudaGetSymbolAddress((void**)&op,  g_op);
    cudaGetSymbolAddress((void**)&ls,  g_ls);
    cudaGetSymbolAddress((void**)&ms,  g_ms);
    cudaGetSymbolAddress((void**)&bc,  g_bc);
    cudaGetSymbolAddress((void**)&c0v, g_c0);
    cudaGetSymbolAddress((void**)&cLv, g_cL);
    cudaGetSymbolAddress((void**)&xi,  g_xi);
    cudaGetSymbolAddress((void**)&qi,  g_qi);
    cudaGetSymbolAddress((void**)&ki,  g_ki);
    cudaGetSymbolAddress((void**)&vi,  g_vi);
    cudaGetSymbolAddress((void**)&wb,  g_wb);

    const dim3 gridCA(4, 3);
    const dim3 gridCV(SEQ/128, BATCH, 3);
    const dim3 gridFL(SEQ/64, BATCH, NSPLIT);
    const dim3 gridPW(NROWS/64);

    compose_all<<<gridCA, 256>>>(wq, wk, wv, wd, bq, bk, bv, bd,
                                 (uint32_t*)wb, bc, c0v, cLv);            // 0
    presplit<<<3*NROWS*16/256, 256>>>(Q, K, V, xi);                       // 1

    cudaFuncSetAttribute(conv3mma,
                         cudaFuncAttributeMaxDynamicSharedMemorySize, CV_SMEM);
    conv3mma<<<gridCV, 256, CV_SMEM>>>(xi, wb, bc, c0v, cLv,
                                       (uint32_t*)qi, (uint32_t*)ki,
                                       (uint32_t*)vi);                    // 2

    cudaFuncSetAttribute(flash_mma12,
                         cudaFuncAttributeMaxDynamicSharedMemorySize, FL_SMEM);
    flash_mma12<<<gridFL, 128, FL_SMEM>>>(qi, ki, vi, op, ls, ms);        // 3

    pw_kernel<<<gridPW, 256>>>(op, ls, ms, wo, bo, out);                  // 4
}

// round 16
// speedup vs baseline: 1.1137x; 1.1019x over previous
#include <cuda_runtime.h>
#include <cuda_bf16.h>
#include <cuda_fp16.h>
#include <stdint.h>

#define BATCH 8
#define SEQ   4096
#define CH    64
#define NROWS (BATCH*SEQ)
#define SP    68
#define NSPLIT 4
#define LOG2E 1.4426950408889634f

// ---------------- scratch (__device__ globals; no allocation) --------------
__device__ uint4 g_xi [(size_t)3*NROWS*16];
__device__ uint4 g_qi [NROWS*16];
__device__ uint4 g_ki [NROWS*16];
__device__ uint4 g_vi [(size_t)BATCH*CH*512];
__device__ uint4 g_wb [3*3072];
__device__ float g_op [(size_t)NSPLIT*NROWS*CH];
__device__ float g_ls [NSPLIT*NROWS];
__device__ float g_ms [NSPLIT*NROWS];
__device__ float g_bc[3][CH];
__device__ float g_c0[3][CH];
__device__ float g_cL[3][CH];

// ---------------- helpers ---------------------------------------------------
__device__ __forceinline__ uint32_t smem_u32(const void* p) {
    uint32_t a;
    asm("{ .reg .u64 t; cvta.to.shared.u64 t, %1; cvt.u32.u64 %0, t; }"
        : "=r"(a) : "l"(p));
    return a;
}
#define CP16(dst, src)  asm volatile("cp.async.cg.shared.global [%0], [%1], 16;" :: "r"(dst), "l"(src))
#define CP_COMMIT()     asm volatile("cp.async.commit_group;" ::: "memory")
#define CP_WAIT(n)      asm volatile("cp.async.wait_group %0;" :: "n"(n) : "memory")

__device__ __forceinline__ void split2(float x, __nv_bfloat16& h, __nv_bfloat16& l) {
    h = __float2bfloat16_rn(x);
    l = __float2bfloat16_rn(x - __bfloat162float(h));
}
__device__ __forceinline__ uint32_t pack2(__nv_bfloat16 a, __nv_bfloat16 b) {
    __nv_bfloat162 p = __halves2bfloat162(a, b);
    return *reinterpret_cast<uint32_t*>(&p);
}
__device__ __forceinline__ uint32_t pack2h(__half a, __half b) {
    __half2 p = __halves2half2(a, b);
    return *reinterpret_cast<uint32_t*>(&p);
}
__device__ __forceinline__ int wmap(int jp) {
    return (jp >> 3)*16 + (jp & 3)*4 + ((jp >> 2) & 1);
}
__device__ __forceinline__ int wmap_v(int jt) {
    return (jt >> 3)*8 + (jt & 3)*2 + ((jt >> 2) & 1);
}
__device__ __forceinline__ void mma_bf16(float c[4],
                                         uint32_t a0, uint32_t a1, uint32_t a2, uint32_t a3,
                                         uint32_t b0, uint32_t b1)
{
    asm volatile("mma.sync.aligned.m16n8k16.row.col.f32.bf16.bf16.f32 "
                 "{%0,%1,%2,%3}, {%4,%5,%6,%7}, {%8,%9}, {%0,%1,%2,%3};\n"
                 : "+f"(c[0]), "+f"(c[1]), "+f"(c[2]), "+f"(c[3])
                 : "r"(a0), "r"(a1), "r"(a2), "r"(a3), "r"(b0), "r"(b1));
}
__device__ __forceinline__ void mma_f16(float c[4],
                                        uint32_t a0, uint32_t a1, uint32_t a2, uint32_t a3,
                                        uint32_t b0, uint32_t b1)
{
    asm volatile("mma.sync.aligned.m16n8k16.row.col.f32.f16.f16.f32 "
                 "{%0,%1,%2,%3}, {%4,%5,%6,%7}, {%8,%9}, {%0,%1,%2,%3};\n"
                 : "+f"(c[0]), "+f"(c[1]), "+f"(c[2]), "+f"(c[3])
                 : "r"(a0), "r"(a1), "r"(a2), "r"(a3), "r"(b0), "r"(b1));
}

// ---------------------------------------------------------------------------
// compose_all
// ---------------------------------------------------------------------------
__global__ __launch_bounds__(256) void compose_all(const float* __restrict__ wq,
                                                   const float* __restrict__ wk,
                                                   const float* __restrict__ wv,
                                                   const float* __restrict__ wd,
                                                   const float* __restrict__ bq,
                                                   const float* __restrict__ bk,
                                                   const float* __restrict__ bv,
                                                   const float* __restrict__ bd,
                                                   uint32_t* __restrict__ wb,
                                                   float* __restrict__ bc,
                                                   float* __restrict__ c0v,
                                                   float* __restrict__ cLv)
{
    const int k = blockIdx.x, chain = blockIdx.y, tid = threadIdx.x;
    const float sgn = (chain == 0) ? LOG2E : 1.f;

    if (k == 3) {
        if (tid < 64) {
            int o = tid;
            const float* b1 = chain == 0 ? bq : (chain == 1 ? bk : bv);
            float s0 = 0.f, s1 = 0.f, s2 = 0.f;
            for (int c = 0; c < CH; c++) {
                float b = b1[c];
                s0 = fmaf(b, wd[0*CH*CH + c*CH + o], s0);
                s1 = fmaf(b, wd[1*CH*CH + c*CH + o], s1);
                s2 = fmaf(b, wd[2*CH*CH + c*CH + o], s2);
            }
            bc [chain*CH + o] = (bd[o] + s0 + s1 + s2)*sgn;
            c0v[chain*CH + o] = s0*sgn;
            cLv[chain*CH + o] = s2*sgn;
        }
        return;
    }

    __shared__ float w1s[CH*CH], wds[CH*CH], wcs[CH*CH];
    const float* w1 = chain == 0 ? wq : (chain == 1 ? wk : wv);
    for (int i = tid; i < CH*CH; i += 256) { w1s[i] = w1[i]; wds[i] = wd[k*CH*CH + i]; }
    __syncthreads();

    {
        int ci = tid >> 2, o0 = (tid & 3) * 16;
        float acc[16] = {};
#pragma unroll 4
        for (int c = 0; c < CH; c++) {
            float a = w1s[ci*CH + c];
#pragma unroll
            for (int j = 0; j < 16; j++) acc[j] = fmaf(a, wds[c*CH + o0 + j], acc[j]);
        }
#pragma unroll
        for (int j = 0; j < 16; j++) wcs[ci*CH + o0 + j] = acc[j]*sgn;
    }
    __syncthreads();

    for (int task = tid; task < 64*32; task += 256) {
        int n = task >> 5, jpl = task & 31;
        float v0 = wcs[(2*jpl)*CH + n];
        float v1 = wcs[(2*jpl + 1)*CH + n];
        __nv_bfloat16 h0, l0, h1, l1;
        split2(v0, h0, l0);
        split2(v1, h1, l1);
        int jp = k*32 + jpl;
        int wx = wmap(jp) ^ ((n & 1) << 4);
        uint32_t* row = wb + (size_t)chain*12288 + n*192;
        row[wx]     = pack2(h0, h1);
        row[wx + 2] = pack2(l0, l1);
    }
}

// ---------------------------------------------------------------------------
// presplit
// ---------------------------------------------------------------------------
__global__ __launch_bounds__(256) void presplit(const float* __restrict__ Q,
                                                const float* __restrict__ K,
                                                const float* __restrict__ V,
                                                uint4* __restrict__ xi)
{
    int gid = blockIdx.x*256 + threadIdx.x;
    int sub = gid & 15;
    int row = gid >> 4;
    int chain = row / NROWS;
    int rowin = row - chain*NROWS;
    const float* X = chain == 0 ? Q : (chain == 1 ? K : V);
    int G = sub >> 2, r = sub & 3;
    int jp0 = G*8 + r, jp1 = jp0 + 4;
    float2 a = *(const float2*)(X + (size_t)rowin*64 + 2*jp0);
    float2 c = *(const float2*)(X + (size_t)rowin*64 + 2*jp1);
    __nv_bfloat16 h0,l0,h1,l1,h2,l2,h3,l3;
    split2(a.x, h0, l0); split2(a.y, h1, l1);
    split2(c.x, h2, l2); split2(c.y, h3, l3);
    uint4 out;
    out.x = pack2(h0, h1);
    out.y = pack2(h2, h3);
    out.z = pack2(l0, l1);
    out.w = pack2(l2, l3);
    int par = (rowin + 1) & 1;
    xi[(size_t)row*16 + ((G ^ par)*4 + r)] = out;
}

// ---------------------------------------------------------------------------
// conv3mma (R13 version: smem-staged weights)
// ---------------------------------------------------------------------------
#define CV_SMEM 82432

__global__ __launch_bounds__(256) void conv3mma(const uint4* __restrict__ XI,
                                                const uint4* __restrict__ WB,
                                                const float* __restrict__ BC,
                                                const float* __restrict__ C0,
                                                const float* __restrict__ CL,
                                                uint32_t* __restrict__ qi,
                                                uint32_t* __restrict__ ki,
                                                uint32_t* __restrict__ vi)
{
    extern __shared__ uint32_t sm[];
    uint32_t* In = sm + 12288;
    const uint32_t sb = smem_u32(sm);
    const int chain = blockIdx.z;
    const int b = blockIdx.y, m0 = blockIdx.x * 128;
    const int tid = threadIdx.x;

    const uint4* wbsrc = WB + (size_t)chain*3072;
    for (int i = tid; i < 3072; i += 256) CP16(sb + i*16, wbsrc + i);
    const uint4* xsrc = XI + (size_t)(chain*NROWS + b*SEQ)*16;
    for (int idx = tid; idx < 130*16; idx += 256) {
        int lr = idx >> 4, q = idx & 15;
        int l = m0 - 1 + lr;
        if (l >= 0 && l < SEQ)
            CP16(sb + 49152 + lr*256 + q*16, xsrc + (size_t)l*16 + q);
        else
            *(uint4*)(In + lr*64 + q*4) = make_uint4(0,0,0,0);
    }
    CP_COMMIT();
    CP_WAIT(0);
    __syncthreads();

    const int lane = tid & 31, w = tid >> 5;
    const int g = lane >> 2, t = lane & 3;
    const int r0 = w*16 + g;

    float acc[8][4] = {};

#pragma unroll
    for (int kt = 0; kt < 12; kt++) {
        const int tap = kt >> 2, ktc = kt & 3;
        const int lr0 = r0 + tap, lr1 = lr0 + 8;
        const int wofs = ktc*16 + t*4;
        uint4 A0 = *(const uint4*)(In + lr0*64 + (wofs ^ ((lr0 & 1) << 4)));
        uint4 A1 = *(const uint4*)(In + lr1*64 + (wofs ^ ((lr1 & 1) << 4)));
#pragma unroll
        for (int nt = 0; nt < 8; nt++) {
            const int bn = nt*8 + g;
            uint4 B = *(const uint4*)(sm + bn*192 + ((kt*16 + t*4) ^ ((bn & 1) << 4)));
            mma_bf16(acc[nt], A0.x, A1.x, A0.y, A1.y, B.x, B.y);
            mma_bf16(acc[nt], A0.x, A1.x, A0.y, A1.y, B.z, B.w);
            mma_bf16(acc[nt], A0.z, A1.z, A0.w, A1.w, B.x, B.y);
        }
    }

    const float* bcp = BC + chain*CH;
    const float* c0p = C0 + chain*CH;
    const float* cLp = CL + chain*CH;
    const int gr0 = m0 + r0;
    const bool first = (gr0 == 0);
    const bool last  = (gr0 + 8 == SEQ - 1);

    if (chain < 2) {
        uint32_t* out = chain == 0 ? qi : ki;
#pragma unroll
        for (int nt = 0; nt < 8; nt++) {
            int n0 = nt*8 + 2*t, n1 = n0 + 1;
            float v00 = acc[nt][0] + __ldg(bcp + n0);
            float v01 = acc[nt][1] + __ldg(bcp + n1);
            float v10 = acc[nt][2] + __ldg(bcp + n0);
            float v11 = acc[nt][3] + __ldg(bcp + n1);
            if (first) { v00 -= __ldg(c0p + n0); v01 -= __ldg(c0p + n1); }
            if (last)  { v10 -= __ldg(cLp + n0); v11 -= __ldg(cLp + n1); }
            int w0 = wmap(nt*4 + t);
            __nv_bfloat16 h0,l0,h1,l1;
            split2(v00, h0, l0); split2(v01, h1, l1);
            out[((size_t)(b*SEQ + gr0))*64 + w0]     = pack2(h0, h1);
            out[((size_t)(b*SEQ + gr0))*64 + w0 + 2] = pack2(l0, l1);
            split2(v10, h0, l0); split2(v11, h1, l1);
            out[((size_t)(b*SEQ + gr0 + 8))*64 + w0]     = pack2(h0, h1);
            out[((size_t)(b*SEQ + gr0 + 8))*64 + w0 + 2] = pack2(l0, l1);
        }
    } else {
#pragma unroll
        for (int nt = 0; nt < 8; nt++) {
            int n0 = nt*8 + 2*t, n1 = n0 + 1;
            float v00 = acc[nt][0] + __ldg(bcp + n0);
            float v01 = acc[nt][1] + __ldg(bcp + n1);
            float v10 = acc[nt][2] + __ldg(bcp + n0);
            float v11 = acc[nt][3] + __ldg(bcp + n1);
            if (first) { v00 -= __ldg(c0p + n0); v01 -= __ldg(c0p + n1); }
            if (last)  { v10 -= __ldg(cLp + n0); v11 -= __ldg(cLp + n1); }
            float p00 = __shfl_xor_sync(0xffffffffu, v00, 4);
            float p01 = __shfl_xor_sync(0xffffffffu, v01, 4);
            float p10 = __shfl_xor_sync(0xffffffffu, v10, 4);
            float p11 = __shfl_xor_sync(0xffffffffu, v11, 4);
            if ((g & 1) == 0) {
                int kp0 = gr0 >> 1;
                int kp1 = (gr0 + 8) >> 1;
                int w0a = wmap_v(kp0 & 31) ^ ((n0 & 3) << 3);
                int w0b = wmap_v(kp0 & 31) ^ ((n1 & 3) << 3);
                int w1a = wmap_v(kp1 & 31) ^ ((n0 & 3) << 3);
                int w1b = wmap_v(kp1 & 31) ^ ((n1 & 3) << 3);
                size_t t0 = (size_t)(kp0 >> 5)*32, t1 = (size_t)(kp1 >> 5)*32;
                uint32_t* row0 = vi + ((size_t)(b*CH + n0))*2048;
                uint32_t* row1 = vi + ((size_t)(b*CH + n1))*2048;
                row0[t0 + w0a] = pack2h(__float2half_rn(v00), __float2half_rn(p00));
                row1[t0 + w0b] = pack2h(__float2half_rn(v01), __float2half_rn(p01));
                row0[t1 + w1a] = pack2h(__float2half_rn(v10), __float2half_rn(p10));
                row1[t1 + w1b] = pack2h(__float2half_rn(v11), __float2half_rn(p11));
            }
        }
    }
}

// ---------------------------------------------------------------------------
// Flash attention: pointer-hoisted staging (constant-stride cp.async),
// QK bf16 3-pass (log2 domain), skip-rescale vote, P fp16, PV fp16 1-pass.
// Split-K = 4, single barrier per tile, interleaved softmax+PV.
// ---------------------------------------------------------------------------
#define FL_SMEM 49152

__global__ __launch_bounds__(128, 3) void flash_mma13(
    const uint4* __restrict__ qi4, const uint4* __restrict__ ki4,
    const uint4* __restrict__ vi4,
    float* __restrict__ OP, float* __restrict__ LS, float* __restrict__ MS)
{
    extern __shared__ uint32_t sm[];
    const uint32_t sb = smem_u32(sm);
    const int tid = threadIdx.x;
    const int lane = tid & 31, w = tid >> 5;
    const int g = lane >> 2, t = lane & 3;
    const int b = blockIdx.y;
    const int m0 = blockIdx.x * 64;
    const int split = blockIdx.z;
    const int kbase = split * (SEQ/NSPLIT);
    const int NT = SEQ/NSPLIT/64;   // 16

    // ---- hoisted staging state (constant strides per rep/tile) ----
    const char* ksrc = (const char*)(ki4 + (size_t)(b*SEQ + kbase + (tid >> 4))*16 + (tid & 15));
    const char* vsrc = (const char*)(vi4 + (size_t)(b*CH + (tid >> 3))*512 + (kbase >> 6)*8 + (tid & 7));
    const uint32_t kdst0 = sb + (uint32_t)((tid >> 4)*256 + (((tid & 15) ^ (((tid >> 4) & 1) << 2))*16));
    const uint32_t vdst0 = sb + (uint32_t)(16384 + (tid >> 3)*128 + (tid & 7)*16);

    uint32_t qhF[4][4], qlF[4][4];
    {
        size_t r0 = (size_t)(b*SEQ + m0 + w*16 + g) * 16;
        size_t r1 = r0 + 8*16;
#pragma unroll
        for (int kt = 0; kt < 4; kt++) {
            uint4 a = __ldg(qi4 + r0 + kt*4 + t);
            uint4 c = __ldg(qi4 + r1 + kt*4 + t);
            qhF[kt][0] = a.x; qhF[kt][2] = a.y; qlF[kt][0] = a.z; qlF[kt][2] = a.w;
            qhF[kt][1] = c.x; qhF[kt][3] = c.y; qlF[kt][1] = c.z; qlF[kt][3] = c.w;
        }
    }

    // ---- prefetch tile 0 into buffer 0 ----
#pragma unroll
    for (int r = 0; r < 8; r++) CP16(kdst0 + r*2048, ksrc + (size_t)r*2048);
#pragma unroll
    for (int r = 0; r < 4; r++) CP16(vdst0 + r*2048, vsrc + (size_t)r*131072);
    CP_COMMIT();
    ksrc += 16384;
    vsrc += 128;

    float oacc[8][4] = {};
    float lsum0 = 0.f, lsum1 = 0.f;
    float mrow0 = -1e30f, mrow1 = -1e30f;

    for (int tt = 0; tt < NT; tt++) {
        CP_WAIT(0);
        __syncthreads();

        const uint32_t* Kt = sm + (size_t)(tt & 1)*6144;
        const uint32_t* Vt = Kt + 4096;
        const int gx = (g & 1) << 4;
        const int gv = (g & 3) << 3;

        // ---- S' = Q K^T (bf16 3-pass, log2-scaled) ----
        float sacc[8][4];
#pragma unroll
        for (int nt = 0; nt < 8; nt++)
#pragma unroll
            for (int c = 0; c < 4; c++) sacc[nt][c] = 0.f;

#pragma unroll
        for (int kt = 0; kt < 4; kt++) {
            const int wofs = (kt*16 + t*4) ^ gx;
#pragma unroll
            for (int nt = 0; nt < 8; nt++) {
                uint4 kf = *(const uint4*)(Kt + (nt*8 + g)*64 + wofs);
                mma_bf16(sacc[nt], qhF[kt][0], qhF[kt][1], qhF[kt][2], qhF[kt][3], kf.x, kf.y);
                mma_bf16(sacc[nt], qhF[kt][0], qhF[kt][1], qhF[kt][2], qhF[kt][3], kf.z, kf.w);
                mma_bf16(sacc[nt], qlF[kt][0], qlF[kt][1], qlF[kt][2], qlF[kt][3], kf.x, kf.y);
            }
        }

        // ---- staging for tile tt+1 (pointer-hoisted, overlaps softmax+PV) ----
        if (tt < NT-1) {
            const uint32_t bs = ((tt + 1) & 1) ? 24576u : 0u;
            const uint32_t kd = kdst0 + bs, vd = vdst0 + bs;
#pragma unroll
            for (int r = 0; r < 8; r++) CP16(kd + r*2048, ksrc + (size_t)r*2048);
#pragma unroll
            for (int r = 0; r < 4; r++) CP16(vd + r*2048, vsrc + (size_t)r*131072);
            CP_COMMIT();
            ksrc += 16384;
            vsrc += 128;
        }

        // ---- softmax header (skip rescale when no row max changed) ----
        float mt0 = -1e30f, mt1 = -1e30f;
#pragma unroll
        for (int nt = 0; nt < 8; nt++) {
            mt0 = fmaxf(mt0, fmaxf(sacc[nt][0], sacc[nt][1]));
            mt1 = fmaxf(mt1, fmaxf(sacc[nt][2], sacc[nt][3]));
        }
        mt0 = fmaxf(mt0, __shfl_xor_sync(0xffffffffu, mt0, 1));
        mt0 = fmaxf(mt0, __shfl_xor_sync(0xffffffffu, mt0, 2));
        mt1 = fmaxf(mt1, __shfl_xor_sync(0xffffffffu, mt1, 1));
        mt1 = fmaxf(mt1, __shfl_xor_sync(0xffffffffu, mt1, 2));
        float mn0 = fmaxf(mrow0, mt0), mn1 = fmaxf(mrow1, mt1);
        bool up = (mn0 > mrow0) || (mn1 > mrow1);
        if (__any_sync(0xffffffffu, up)) {
            float sc0 = exp2f(mrow0 - mn0), sc1 = exp2f(mrow1 - mn1);
            lsum0 *= sc0; lsum1 *= sc1;
#pragma unroll
            for (int nt = 0; nt < 8; nt++) {
                oacc[nt][0] *= sc0; oacc[nt][1] *= sc0;
                oacc[nt][2] *= sc1; oacc[nt][3] *= sc1;
            }
            mrow0 = mn0; mrow1 = mn1;
        }

        // ---- interleaved exp2/pack + PV HMMAs ----
#pragma unroll
        for (int kt = 0; kt < 4; kt++) {
            const int a = 2*kt, b2 = 2*kt + 1;
            float e00 = exp2f(sacc[a][0]  - mrow0);
            float e01 = exp2f(sacc[a][1]  - mrow0);
            float e02 = exp2f(sacc[a][2]  - mrow1);
            float e03 = exp2f(sacc[a][3]  - mrow1);
            float e10 = exp2f(sacc[b2][0] - mrow0);
            float e11 = exp2f(sacc[b2][1] - mrow0);
            float e12 = exp2f(sacc[b2][2] - mrow1);
            float e13 = exp2f(sacc[b2][3] - mrow1);
            lsum0 += e00 + e01 + e10 + e11;
            lsum1 += e02 + e03 + e12 + e13;
            uint32_t ah0 = pack2h(__float2half_rn(e00), __float2half_rn(e01));
            uint32_t ah1 = pack2h(__float2half_rn(e02), __float2half_rn(e03));
            uint32_t ah2 = pack2h(__float2half_rn(e10), __float2half_rn(e11));
            uint32_t ah3 = pack2h(__float2half_rn(e12), __float2half_rn(e13));
            const int widx = (kt*8 + t*2) ^ gv;
#pragma unroll
            for (int nt = 0; nt < 8; nt++) {
                uint2 vf = *(const uint2*)(Vt + (nt*8 + g)*32 + widx);
                mma_f16(oacc[nt], ah0, ah1, ah2, ah3, vf.x, vf.y);
            }
        }
    }

    lsum0 += __shfl_xor_sync(0xffffffffu, lsum0, 1);
    lsum0 += __shfl_xor_sync(0xffffffffu, lsum0, 2);
    lsum1 += __shfl_xor_sync(0xffffffffu, lsum1, 1);
    lsum1 += __shfl_xor_sync(0xffffffffu, lsum1, 2);

    const size_t row0 = (size_t)(b*SEQ + m0 + w*16 + g);
    const size_t row1 = row0 + 8;
    if (t == 0) {
        LS[(size_t)split*NROWS + row0] = lsum0;
        LS[(size_t)split*NROWS + row1] = lsum1;
        MS[(size_t)split*NROWS + row0] = mrow0;
        MS[(size_t)split*NROWS + row1] = mrow1;
    }

    float* op = OP + (size_t)split*NROWS*CH;
#pragma unroll
    for (int nt = 0; nt < 8; nt++) {
        *(float2*)(op + row0*CH + nt*8 + 2*t) = make_float2(oacc[nt][0], oacc[nt][1]);
        *(float2*)(op + row1*CH + nt*8 + 2*t) = make_float2(oacc[nt][2], oacc[nt][3]);
    }
}

// ---------------------------------------------------------------------------
// Output pointwise conv, 4-way max-aware split-K combine (log2 domain).
// ---------------------------------------------------------------------------
__global__ __launch_bounds__(256) void pw_kernel(const float* __restrict__ OP,
                                                 const float* __restrict__ LS,
                                                 const float* __restrict__ MS,
                                                 const float* __restrict__ W,
                                                 const float* __restrict__ bias,
                                                 float* __restrict__ Y)
{
    __shared__ float Xs[CH*SP];
    __shared__ float Ws[CH*SP];
    __shared__ float as[NSPLIT][64];
    const int  tid  = threadIdx.x;
    const size_t base = (size_t)blockIdx.x * 64;

    if (tid < 64) {
        size_t r = base + tid;
        float m[NSPLIT], M = -1e30f;
#pragma unroll
        for (int s = 0; s < NSPLIT; s++) { m[s] = MS[(size_t)s*NROWS + r]; M = fmaxf(M, m[s]); }
        float wgt[NSPLIT], denom = 0.f;
#pragma unroll
        for (int s = 0; s < NSPLIT; s++) {
            wgt[s] = exp2f(m[s] - M);
            denom = fmaf(LS[(size_t)s*NROWS + r], wgt[s], denom);
        }
        float inv = 1.f / denom;
#pragma unroll
        for (int s = 0; s < NSPLIT; s++) as[s][tid] = wgt[s]*inv;
    }
    __syncthreads();

#pragma unroll
    for (int rep = 0; rep < 4; rep++) {
        int idx = tid + rep*256;
        int r = idx >> 4, q = idx & 15;
        float x0 = 0.f, x1 = 0.f, x2 = 0.f, x3 = 0.f;
#pragma unroll
        for (int s = 0; s < NSPLIT; s++) {
            float a = as[s][r];
            float4 xv = *(const float4*)(OP + (size_t)s*NROWS*CH + (base + r)*CH + q*4);
            x0 = fmaf(xv.x, a, x0);
            x1 = fmaf(xv.y, a, x1);
            x2 = fmaf(xv.z, a, x2);
            x3 = fmaf(xv.w, a, x3);
        }
        Xs[(q*4+0)*SP + r] = x0;
        Xs[(q*4+1)*SP + r] = x1;
        Xs[(q*4+2)*SP + r] = x2;
        Xs[(q*4+3)*SP + r] = x3;
        *(float4*)(Ws + r*SP + q*4) = *(const float4*)(W + idx*4);
    }
    __syncthreads();

    const int tx = tid & 15, ty = tid >> 4;
    const int i0 = ty*4,  c0 = tx*4;
    float acc[4][4] = {};

#pragma unroll 8
    for (int ci = 0; ci < CH; ci++) {
        float4 a4 = *(const float4*)(Xs + ci*SP + i0);
        float4 w4 = *(const float4*)(Ws + ci*SP + c0);
        float a[4] = {a4.x, a4.y, a4.z, a4.w};
        float w[4] = {w4.x, w4.y, w4.z, w4.w};
#pragma unroll
        for (int ii = 0; ii < 4; ii++)
#pragma unroll
            for (int jj = 0; jj < 4; jj++)
                acc[ii][jj] = fmaf(a[ii], w[jj], acc[ii][jj]);
    }

    float4 bv = *(const float4*)(bias + c0);
#pragma unroll
    for (int ii = 0; ii < 4; ii++) {
        float4 o;
        o.x = acc[ii][0] + bv.x;
        o.y = acc[ii][1] + bv.y;
        o.z = acc[ii][2] + bv.z;
        o.w = acc[ii][3] + bv.w;
        *(float4*)(Y + (base + i0 + ii)*CH + c0) = o;
    }
}

// ---------------------------------------------------------------------------
extern "C" void kernel_launch(void* const* d_in, const int* in_sizes, int n_in,
                              void* d_out, int out_size)
{
    const float* Q  = (const float*)d_in[0];
    const float* K  = (const float*)d_in[1];
    const float* V  = (const float*)d_in[2];
    const float* wq = (const float*)d_in[3];
    const float* bq = (const float*)d_in[4];
    const float* wk = (const float*)d_in[5];
    const float* bk = (const float*)d_in[6];
    const float* wv = (const float*)d_in[7];
    const float* bv = (const float*)d_in[8];
    const float* wd = (const float*)d_in[9];
    const float* bd = (const float*)d_in[10];
    const float* wo = (const float*)d_in[11];
    const float* bo = (const float*)d_in[12];
    float* out = (float*)d_out;

    float *op, *ls, *ms, *bc, *c0v, *cLv;
    uint4 *xi, *qi, *ki, *vi, *wb;
    cudaGetSymbolAddress((void**)&op,  g_op);
    cudaGetSymbolAddress((void**)&ls,  g_ls);
    cudaGetSymbolAddress((void**)&ms,  g_ms);
    cudaGetSymbolAddress((void**)&bc,  g_bc);
    cudaGetSymbolAddress((void**)&c0v, g_c0);
    cudaGetSymbolAddress((void**)&cLv, g_cL);
    cudaGetSymbolAddress((void**)&xi,  g_xi);
    cudaGetSymbolAddress((void**)&qi,  g_qi);
    cudaGetSymbolAddress((void**)&ki,  g_ki);
    cudaGetSymbolAddress((void**)&vi,  g_vi);
    cudaGetSymbolAddress((void**)&wb,  g_wb);

    const dim3 gridCA(4, 3);
    const dim3 gridCV(SEQ/128, BATCH, 3);
    const dim3 gridFL(SEQ/64, BATCH, NSPLIT);
    const dim3 gridPW(NROWS/64);

    compose_all<<<gridCA, 256>>>(wq, wk, wv, wd, bq, bk, bv, bd,
                                 (uint32_t*)wb, bc, c0v, cLv);            // 0
    presplit<<<3*NROWS*16/256, 256>>>(Q, K, V, xi);                       // 1

    cudaFuncSetAttribute(conv3mma,
                         cudaFuncAttributeMaxDynamicSharedMemorySize, CV_SMEM);
    conv3mma<<<gridCV, 256, CV_SMEM>>>(xi, wb, bc, c0v, cLv,
                                       (uint32_t*)qi, (uint32_t*)ki,
                                       (uint32_t*)vi);                    // 2

    cudaFuncSetAttribute(flash_mma13,
                         cudaFuncAttributeMaxDynamicSharedMemorySize, FL_SMEM);
    flash_mma13<<<gridFL, 128, FL_SMEM>>>(qi, ki, vi, op, ls, ms);        // 3

    pw_kernel<<<gridPW, 256>>>(op, ls, ms, wo, bo, out);                  // 4
}

// round 17
// speedup vs baseline: 1.1172x; 1.0031x over previous
#include <cuda_runtime.h>
#include <cuda_bf16.h>
#include <cuda_fp16.h>
#include <stdint.h>

#define BATCH 8
#define SEQ   4096
#define CH    64
#define NROWS (BATCH*SEQ)
#define SP    68
#define NSPLIT 4
#define LOG2E 1.4426950408889634f

// ---------------- scratch (__device__ globals; no allocation) --------------
__device__ uint4 g_xi [(size_t)3*NROWS*16];
__device__ uint4 g_qi [NROWS*16];
__device__ uint4 g_ki [NROWS*16];
__device__ uint4 g_vi [(size_t)BATCH*CH*512];
__device__ uint4 g_wb [3*3072];
__device__ uint32_t g_oph [(size_t)NSPLIT*NROWS*32];   // normalized O, half2 pairs
__device__ float g_ls [NSPLIT*NROWS];
__device__ float g_ms [NSPLIT*NROWS];
__device__ float g_bc[3][CH];
__device__ float g_c0[3][CH];
__device__ float g_cL[3][CH];

// ---------------- helpers ---------------------------------------------------
__device__ __forceinline__ uint32_t smem_u32(const void* p) {
    uint32_t a;
    asm("{ .reg .u64 t; cvta.to.shared.u64 t, %1; cvt.u32.u64 %0, t; }"
        : "=r"(a) : "l"(p));
    return a;
}
#define CP16(dst, src)  asm volatile("cp.async.cg.shared.global [%0], [%1], 16;" :: "r"(dst), "l"(src))
#define CP_COMMIT()     asm volatile("cp.async.commit_group;" ::: "memory")
#define CP_WAIT(n)      asm volatile("cp.async.wait_group %0;" :: "n"(n) : "memory")

__device__ __forceinline__ void split2(float x, __nv_bfloat16& h, __nv_bfloat16& l) {
    h = __float2bfloat16_rn(x);
    l = __float2bfloat16_rn(x - __bfloat162float(h));
}
__device__ __forceinline__ uint32_t pack2(__nv_bfloat16 a, __nv_bfloat16 b) {
    __nv_bfloat162 p = __halves2bfloat162(a, b);
    return *reinterpret_cast<uint32_t*>(&p);
}
__device__ __forceinline__ uint32_t pack2h(__half a, __half b) {
    __half2 p = __halves2half2(a, b);
    return *reinterpret_cast<uint32_t*>(&p);
}
__device__ __forceinline__ int wmap(int jp) {
    return (jp >> 3)*16 + (jp & 3)*4 + ((jp >> 2) & 1);
}
// V layout v2: word for key-pair jt at channel n (paired-kt LDS.128 fragments)
__device__ __forceinline__ int vmap2(int jt, int n) {
    int kt = jt >> 3, tt = jt & 3, bb = (jt >> 2) & 1;
    int gi = tt*2 + (kt >> 1);
    int inner = (kt & 1)*2 + bb;
    return ((gi ^ (n & 7)) << 2) | inner;
}
__device__ __forceinline__ void mma_bf16(float c[4],
                                         uint32_t a0, uint32_t a1, uint32_t a2, uint32_t a3,
                                         uint32_t b0, uint32_t b1)
{
    asm volatile("mma.sync.aligned.m16n8k16.row.col.f32.bf16.bf16.f32 "
                 "{%0,%1,%2,%3}, {%4,%5,%6,%7}, {%8,%9}, {%0,%1,%2,%3};\n"
                 : "+f"(c[0]), "+f"(c[1]), "+f"(c[2]), "+f"(c[3])
                 : "r"(a0), "r"(a1), "r"(a2), "r"(a3), "r"(b0), "r"(b1));
}
__device__ __forceinline__ void mma_f16(float c[4],
                                        uint32_t a0, uint32_t a1, uint32_t a2, uint32_t a3,
                                        uint32_t b0, uint32_t b1)
{
    asm volatile("mma.sync.aligned.m16n8k16.row.col.f32.f16.f16.f32 "
                 "{%0,%1,%2,%3}, {%4,%5,%6,%7}, {%8,%9}, {%0,%1,%2,%3};\n"
                 : "+f"(c[0]), "+f"(c[1]), "+f"(c[2]), "+f"(c[3])
                 : "r"(a0), "r"(a1), "r"(a2), "r"(a3), "r"(b0), "r"(b1));
}

// ---------------------------------------------------------------------------
// compose_all
// ---------------------------------------------------------------------------
__global__ __launch_bounds__(256) void compose_all(const float* __restrict__ wq,
                                                   const float* __restrict__ wk,
                                                   const float* __restrict__ wv,
                                                   const float* __restrict__ wd,
                                                   const float* __restrict__ bq,
                                                   const float* __restrict__ bk,
                                                   const float* __restrict__ bv,
                                                   const float* __restrict__ bd,
                                                   uint32_t* __restrict__ wb,
                                                   float* __restrict__ bc,
                                                   float* __restrict__ c0v,
                                                   float* __restrict__ cLv)
{
    const int k = blockIdx.x, chain = blockIdx.y, tid = threadIdx.x;
    const float sgn = (chain == 0) ? LOG2E : 1.f;

    if (k == 3) {
        if (tid < 64) {
            int o = tid;
            const float* b1 = chain == 0 ? bq : (chain == 1 ? bk : bv);
            float s0 = 0.f, s1 = 0.f, s2 = 0.f;
            for (int c = 0; c < CH; c++) {
                float b = b1[c];
                s0 = fmaf(b, wd[0*CH*CH + c*CH + o], s0);
                s1 = fmaf(b, wd[1*CH*CH + c*CH + o], s1);
                s2 = fmaf(b, wd[2*CH*CH + c*CH + o], s2);
            }
            bc [chain*CH + o] = (bd[o] + s0 + s1 + s2)*sgn;
            c0v[chain*CH + o] = s0*sgn;
            cLv[chain*CH + o] = s2*sgn;
        }
        return;
    }

    __shared__ float w1s[CH*CH], wds[CH*CH], wcs[CH*CH];
    const float* w1 = chain == 0 ? wq : (chain == 1 ? wk : wv);
    for (int i = tid; i < CH*CH; i += 256) { w1s[i] = w1[i]; wds[i] = wd[k*CH*CH + i]; }
    __syncthreads();

    {
        int ci = tid >> 2, o0 = (tid & 3) * 16;
        float acc[16] = {};
#pragma unroll 4
        for (int c = 0; c < CH; c++) {
            float a = w1s[ci*CH + c];
#pragma unroll
            for (int j = 0; j < 16; j++) acc[j] = fmaf(a, wds[c*CH + o0 + j], acc[j]);
        }
#pragma unroll
        for (int j = 0; j < 16; j++) wcs[ci*CH + o0 + j] = acc[j]*sgn;
    }
    __syncthreads();

    for (int task = tid; task < 64*32; task += 256) {
        int n = task >> 5, jpl = task & 31;
        float v0 = wcs[(2*jpl)*CH + n];
        float v1 = wcs[(2*jpl + 1)*CH + n];
        __nv_bfloat16 h0, l0, h1, l1;
        split2(v0, h0, l0);
        split2(v1, h1, l1);
        int jp = k*32 + jpl;
        int wx = wmap(jp) ^ ((n & 1) << 4);
        uint32_t* row = wb + (size_t)chain*12288 + n*192;
        row[wx]     = pack2(h0, h1);
        row[wx + 2] = pack2(l0, l1);
    }
}

// ---------------------------------------------------------------------------
// presplit
// ---------------------------------------------------------------------------
__global__ __launch_bounds__(256) void presplit(const float* __restrict__ Q,
                                                const float* __restrict__ K,
                                                const float* __restrict__ V,
                                                uint4* __restrict__ xi)
{
    int gid = blockIdx.x*256 + threadIdx.x;
    int sub = gid & 15;
    int row = gid >> 4;
    int chain = row / NROWS;
    int rowin = row - chain*NROWS;
    const float* X = chain == 0 ? Q : (chain == 1 ? K : V);
    int G = sub >> 2, r = sub & 3;
    int jp0 = G*8 + r, jp1 = jp0 + 4;
    float2 a = *(const float2*)(X + (size_t)rowin*64 + 2*jp0);
    float2 c = *(const float2*)(X + (size_t)rowin*64 + 2*jp1);
    __nv_bfloat16 h0,l0,h1,l1,h2,l2,h3,l3;
    split2(a.x, h0, l0); split2(a.y, h1, l1);
    split2(c.x, h2, l2); split2(c.y, h3, l3);
    uint4 out;
    out.x = pack2(h0, h1);
    out.y = pack2(h2, h3);
    out.z = pack2(l0, l1);
    out.w = pack2(l2, l3);
    int par = (rowin + 1) & 1;
    xi[(size_t)row*16 + ((G ^ par)*4 + r)] = out;
}

// ---------------------------------------------------------------------------
// conv3mma (smem-staged weights; V writer uses vmap2 layout)
// ---------------------------------------------------------------------------
#define CV_SMEM 82432

__global__ __launch_bounds__(256) void conv3mma(const uint4* __restrict__ XI,
                                                const uint4* __restrict__ WB,
                                                const float* __restrict__ BC,
                                                const float* __restrict__ C0,
                                                const float* __restrict__ CL,
                                                uint32_t* __restrict__ qi,
                                                uint32_t* __restrict__ ki,
                                                uint32_t* __restrict__ vi)
{
    extern __shared__ uint32_t sm[];
    uint32_t* In = sm + 12288;
    const uint32_t sb = smem_u32(sm);
    const int chain = blockIdx.z;
    const int b = blockIdx.y, m0 = blockIdx.x * 128;
    const int tid = threadIdx.x;

    const uint4* wbsrc = WB + (size_t)chain*3072;
    for (int i = tid; i < 3072; i += 256) CP16(sb + i*16, wbsrc + i);
    const uint4* xsrc = XI + (size_t)(chain*NROWS + b*SEQ)*16;
    for (int idx = tid; idx < 130*16; idx += 256) {
        int lr = idx >> 4, q = idx & 15;
        int l = m0 - 1 + lr;
        if (l >= 0 && l < SEQ)
            CP16(sb + 49152 + lr*256 + q*16, xsrc + (size_t)l*16 + q);
        else
            *(uint4*)(In + lr*64 + q*4) = make_uint4(0,0,0,0);
    }
    CP_COMMIT();
    CP_WAIT(0);
    __syncthreads();

    const int lane = tid & 31, w = tid >> 5;
    const int g = lane >> 2, t = lane & 3;
    const int r0 = w*16 + g;

    float acc[8][4] = {};

#pragma unroll
    for (int kt = 0; kt < 12; kt++) {
        const int tap = kt >> 2, ktc = kt & 3;
        const int lr0 = r0 + tap, lr1 = lr0 + 8;
        const int wofs = ktc*16 + t*4;
        uint4 A0 = *(const uint4*)(In + lr0*64 + (wofs ^ ((lr0 & 1) << 4)));
        uint4 A1 = *(const uint4*)(In + lr1*64 + (wofs ^ ((lr1 & 1) << 4)));
#pragma unroll
        for (int nt = 0; nt < 8; nt++) {
            const int bn = nt*8 + g;
            uint4 B = *(const uint4*)(sm + bn*192 + ((kt*16 + t*4) ^ ((bn & 1) << 4)));
            mma_bf16(acc[nt], A0.x, A1.x, A0.y, A1.y, B.x, B.y);
            mma_bf16(acc[nt], A0.x, A1.x, A0.y, A1.y, B.z, B.w);
            mma_bf16(acc[nt], A0.z, A1.z, A0.w, A1.w, B.x, B.y);
        }
    }

    const float* bcp = BC + chain*CH;
    const float* c0p = C0 + chain*CH;
    const float* cLp = CL + chain*CH;
    const int gr0 = m0 + r0;
    const bool first = (gr0 == 0);
    const bool last  = (gr0 + 8 == SEQ - 1);

    if (chain < 2) {
        uint32_t* out = chain == 0 ? qi : ki;
#pragma unroll
        for (int nt = 0; nt < 8; nt++) {
            int n0 = nt*8 + 2*t, n1 = n0 + 1;
            float v00 = acc[nt][0] + __ldg(bcp + n0);
            float v01 = acc[nt][1] + __ldg(bcp + n1);
            float v10 = acc[nt][2] + __ldg(bcp + n0);
            float v11 = acc[nt][3] + __ldg(bcp + n1);
            if (first) { v00 -= __ldg(c0p + n0); v01 -= __ldg(c0p + n1); }
            if (last)  { v10 -= __ldg(cLp + n0); v11 -= __ldg(cLp + n1); }
            int w0 = wmap(nt*4 + t);
            __nv_bfloat16 h0,l0,h1,l1;
            split2(v00, h0, l0); split2(v01, h1, l1);
            out[((size_t)(b*SEQ + gr0))*64 + w0]     = pack2(h0, h1);
            out[((size_t)(b*SEQ + gr0))*64 + w0 + 2] = pack2(l0, l1);
            split2(v10, h0, l0); split2(v11, h1, l1);
            out[((size_t)(b*SEQ + gr0 + 8))*64 + w0]     = pack2(h0, h1);
            out[((size_t)(b*SEQ + gr0 + 8))*64 + w0 + 2] = pack2(l0, l1);
        }
    } else {
#pragma unroll
        for (int nt = 0; nt < 8; nt++) {
            int n0 = nt*8 + 2*t, n1 = n0 + 1;
            float v00 = acc[nt][0] + __ldg(bcp + n0);
            float v01 = acc[nt][1] + __ldg(bcp + n1);
            float v10 = acc[nt][2] + __ldg(bcp + n0);
            float v11 = acc[nt][3] + __ldg(bcp + n1);
            if (first) { v00 -= __ldg(c0p + n0); v01 -= __ldg(c0p + n1); }
            if (last)  { v10 -= __ldg(cLp + n0); v11 -= __ldg(cLp + n1); }
            float p00 = __shfl_xor_sync(0xffffffffu, v00, 4);
            float p01 = __shfl_xor_sync(0xffffffffu, v01, 4);
            float p10 = __shfl_xor_sync(0xffffffffu, v10, 4);
            float p11 = __shfl_xor_sync(0xffffffffu, v11, 4);
            if ((g & 1) == 0) {
                int kp0 = gr0 >> 1;
                int kp1 = (gr0 + 8) >> 1;
                int jt0 = kp0 & 31, jt1 = kp1 & 31;
                size_t t0 = (size_t)(kp0 >> 5)*32, t1 = (size_t)(kp1 >> 5)*32;
                uint32_t* row0 = vi + ((size_t)(b*CH + n0))*2048;
                uint32_t* row1 = vi + ((size_t)(b*CH + n1))*2048;
                row0[t0 + vmap2(jt0, n0)] = pack2h(__float2half_rn(v00), __float2half_rn(p00));
                row1[t0 + vmap2(jt0, n1)] = pack2h(__float2half_rn(v01), __float2half_rn(p01));
                row0[t1 + vmap2(jt1, n0)] = pack2h(__float2half_rn(v10), __float2half_rn(p10));
                row1[t1 + vmap2(jt1, n1)] = pack2h(__float2half_rn(v11), __float2half_rn(p11));
            }
        }
    }
}

// ---------------------------------------------------------------------------
// Flash attention: pointer-hoisted staging, QK bf16 3-pass (log2 domain),
// skip-rescale vote, P fp16, PV fp16 1-pass with paired-kt LDS.128 V frags.
// Epilogue normalizes and stores half2. Split-K = 4.
// ---------------------------------------------------------------------------
#define FL_SMEM 49152

__global__ __launch_bounds__(128, 3) void flash_mma14(
    const uint4* __restrict__ qi4, const uint4* __restrict__ ki4,
    const uint4* __restrict__ vi4,
    uint32_t* __restrict__ OPh, float* __restrict__ LS, float* __restrict__ MS)
{
    extern __shared__ uint32_t sm[];
    const uint32_t sb = smem_u32(sm);
    const int tid = threadIdx.x;
    const int lane = tid & 31, w = tid >> 5;
    const int g = lane >> 2, t = lane & 3;
    const int b = blockIdx.y;
    const int m0 = blockIdx.x * 64;
    const int split = blockIdx.z;
    const int kbase = split * (SEQ/NSPLIT);
    const int NT = SEQ/NSPLIT/64;   // 16

    // ---- hoisted staging state ----
    const char* ksrc = (const char*)(ki4 + (size_t)(b*SEQ + kbase + (tid >> 4))*16 + (tid & 15));
    const char* vsrc = (const char*)(vi4 + (size_t)(b*CH + (tid >> 3))*512 + (kbase >> 6)*8 + (tid & 7));
    const uint32_t kdst0 = sb + (uint32_t)((tid >> 4)*256 + (((tid & 15) ^ (((tid >> 4) & 1) << 2))*16));
    const uint32_t vdst0 = sb + (uint32_t)(16384 + (tid >> 3)*128 + (tid & 7)*16);

    uint32_t qhF[4][4], qlF[4][4];
    {
        size_t r0 = (size_t)(b*SEQ + m0 + w*16 + g) * 16;
        size_t r1 = r0 + 8*16;
#pragma unroll
        for (int kt = 0; kt < 4; kt++) {
            uint4 a = __ldg(qi4 + r0 + kt*4 + t);
            uint4 c = __ldg(qi4 + r1 + kt*4 + t);
            qhF[kt][0] = a.x; qhF[kt][2] = a.y; qlF[kt][0] = a.z; qlF[kt][2] = a.w;
            qhF[kt][1] = c.x; qhF[kt][3] = c.y; qlF[kt][1] = c.z; qlF[kt][3] = c.w;
        }
    }

    // ---- prefetch tile 0 ----
#pragma unroll
    for (int r = 0; r < 8; r++) CP16(kdst0 + r*2048, ksrc + (size_t)r*2048);
#pragma unroll
    for (int r = 0; r < 4; r++) CP16(vdst0 + r*2048, vsrc + (size_t)r*131072);
    CP_COMMIT();
    ksrc += 16384;
    vsrc += 128;

    float oacc[8][4] = {};
    float lsum0 = 0.f, lsum1 = 0.f;
    float mrow0 = -1e30f, mrow1 = -1e30f;

    for (int tt = 0; tt < NT; tt++) {
        CP_WAIT(0);
        __syncthreads();

        const uint32_t* Kt = sm + (size_t)(tt & 1)*6144;
        const uint32_t* Vt = Kt + 4096;
        const int gx = (g & 1) << 4;

        // ---- S' = Q K^T (bf16 3-pass, log2-scaled) ----
        float sacc[8][4];
#pragma unroll
        for (int nt = 0; nt < 8; nt++)
#pragma unroll
            for (int c = 0; c < 4; c++) sacc[nt][c] = 0.f;

#pragma unroll
        for (int kt = 0; kt < 4; kt++) {
            const int wofs = (kt*16 + t*4) ^ gx;
#pragma unroll
            for (int nt = 0; nt < 8; nt++) {
                uint4 kf = *(const uint4*)(Kt + (nt*8 + g)*64 + wofs);
                mma_bf16(sacc[nt], qhF[kt][0], qhF[kt][1], qhF[kt][2], qhF[kt][3], kf.x, kf.y);
                mma_bf16(sacc[nt], qhF[kt][0], qhF[kt][1], qhF[kt][2], qhF[kt][3], kf.z, kf.w);
                mma_bf16(sacc[nt], qlF[kt][0], qlF[kt][1], qlF[kt][2], qlF[kt][3], kf.x, kf.y);
            }
        }

        // ---- staging for tile tt+1 ----
        if (tt < NT-1) {
            const uint32_t bs = ((tt + 1) & 1) ? 24576u : 0u;
            const uint32_t kd = kdst0 + bs, vd = vdst0 + bs;
#pragma unroll
            for (int r = 0; r < 8; r++) CP16(kd + r*2048, ksrc + (size_t)r*2048);
#pragma unroll
            for (int r = 0; r < 4; r++) CP16(vd + r*2048, vsrc + (size_t)r*131072);
            CP_COMMIT();
            ksrc += 16384;
            vsrc += 128;
        }

        // ---- softmax header (skip rescale when no row max changed) ----
        float mt0 = -1e30f, mt1 = -1e30f;
#pragma unroll
        for (int nt = 0; nt < 8; nt++) {
            mt0 = fmaxf(mt0, fmaxf(sacc[nt][0], sacc[nt][1]));
            mt1 = fmaxf(mt1, fmaxf(sacc[nt][2], sacc[nt][3]));
        }
        mt0 = fmaxf(mt0, __shfl_xor_sync(0xffffffffu, mt0, 1));
        mt0 = fmaxf(mt0, __shfl_xor_sync(0xffffffffu, mt0, 2));
        mt1 = fmaxf(mt1, __shfl_xor_sync(0xffffffffu, mt1, 1));
        mt1 = fmaxf(mt1, __shfl_xor_sync(0xffffffffu, mt1, 2));
        float mn0 = fmaxf(mrow0, mt0), mn1 = fmaxf(mrow1, mt1);
        bool up = (mn0 > mrow0) || (mn1 > mrow1);
        if (__any_sync(0xffffffffu, up)) {
            float sc0 = exp2f(mrow0 - mn0), sc1 = exp2f(mrow1 - mn1);
            lsum0 *= sc0; lsum1 *= sc1;
#pragma unroll
            for (int nt = 0; nt < 8; nt++) {
                oacc[nt][0] *= sc0; oacc[nt][1] *= sc0;
                oacc[nt][2] *= sc1; oacc[nt][3] *= sc1;
            }
            mrow0 = mn0; mrow1 = mn1;
        }

        // ---- interleaved exp2/pack + PV HMMAs (paired kt, LDS.128 V) ----
#pragma unroll
        for (int p = 0; p < 2; p++) {
            const int ka = 2*p, kb2 = 2*p + 1;
            // kt = ka
            float ea00 = exp2f(sacc[2*ka][0]   - mrow0);
            float ea01 = exp2f(sacc[2*ka][1]   - mrow0);
            float ea02 = exp2f(sacc[2*ka][2]   - mrow1);
            float ea03 = exp2f(sacc[2*ka][3]   - mrow1);
            float ea10 = exp2f(sacc[2*ka+1][0] - mrow0);
            float ea11 = exp2f(sacc[2*ka+1][1] - mrow0);
            float ea12 = exp2f(sacc[2*ka+1][2] - mrow1);
            float ea13 = exp2f(sacc[2*ka+1][3] - mrow1);
            // kt = kb2
            float eb00 = exp2f(sacc[2*kb2][0]   - mrow0);
            float eb01 = exp2f(sacc[2*kb2][1]   - mrow0);
            float eb02 = exp2f(sacc[2*kb2][2]   - mrow1);
            float eb03 = exp2f(sacc[2*kb2][3]   - mrow1);
            float eb10 = exp2f(sacc[2*kb2+1][0] - mrow0);
            float eb11 = exp2f(sacc[2*kb2+1][1] - mrow0);
            float eb12 = exp2f(sacc[2*kb2+1][2] - mrow1);
            float eb13 = exp2f(sacc[2*kb2+1][3] - mrow1);
            lsum0 += ea00 + ea01 + ea10 + ea11 + eb00 + eb01 + eb10 + eb11;
            lsum1 += ea02 + ea03 + ea12 + ea13 + eb02 + eb03 + eb12 + eb13;
            uint32_t aA0 = pack2h(__float2half_rn(ea00), __float2half_rn(ea01));
            uint32_t aA1 = pack2h(__float2half_rn(ea02), __float2half_rn(ea03));
            uint32_t aA2 = pack2h(__float2half_rn(ea10), __float2half_rn(ea11));
            uint32_t aA3 = pack2h(__float2half_rn(ea12), __float2half_rn(ea13));
            uint32_t aB0 = pack2h(__float2half_rn(eb00), __float2half_rn(eb01));
            uint32_t aB1 = pack2h(__float2half_rn(eb02), __float2half_rn(eb03));
            uint32_t aB2 = pack2h(__float2half_rn(eb10), __float2half_rn(eb11));
            uint32_t aB3 = pack2h(__float2half_rn(eb12), __float2half_rn(eb13));
            const int widx = ((t*2 + p) ^ (g & 7)) << 2;
#pragma unroll
            for (int nt = 0; nt < 8; nt++) {
                uint4 vf = *(const uint4*)(Vt + (nt*8 + g)*32 + widx);
                mma_f16(oacc[nt], aA0, aA1, aA2, aA3, vf.x, vf.y);
                mma_f16(oacc[nt], aB0, aB1, aB2, aB3, vf.z, vf.w);
            }
        }
    }

    lsum0 += __shfl_xor_sync(0xffffffffu, lsum0, 1);
    lsum0 += __shfl_xor_sync(0xffffffffu, lsum0, 2);
    lsum1 += __shfl_xor_sync(0xffffffffu, lsum1, 1);
    lsum1 += __shfl_xor_sync(0xffffffffu, lsum1, 2);

    const size_t row0 = (size_t)(b*SEQ + m0 + w*16 + g);
    const size_t row1 = row0 + 8;
    if (t == 0) {
        LS[(size_t)split*NROWS + row0] = lsum0;
        LS[(size_t)split*NROWS + row1] = lsum1;
        MS[(size_t)split*NROWS + row0] = mrow0;
        MS[(size_t)split*NROWS + row1] = mrow1;
    }

    float inv0 = 1.f / lsum0;
    float inv1 = 1.f / lsum1;
    uint32_t* oph = OPh + (size_t)split*NROWS*32;
#pragma unroll
    for (int nt = 0; nt < 8; nt++) {
        oph[row0*32 + nt*4 + t] = pack2h(__float2half_rn(oacc[nt][0]*inv0),
                                         __float2half_rn(oacc[nt][1]*inv0));
        oph[row1*32 + nt*4 + t] = pack2h(__float2half_rn(oacc[nt][2]*inv1),
                                         __float2half_rn(oacc[nt][3]*inv1));
    }
}

// ---------------------------------------------------------------------------
// Output pointwise conv, 4-way combine of normalized half2 partials:
//   X = sum_s alpha_s * o_s,  alpha_s = l_s*2^(m_s-M) / sum(l*w)
// ---------------------------------------------------------------------------
__global__ __launch_bounds__(256) void pw_kernel(const uint32_t* __restrict__ OPh,
                                                 const float* __restrict__ LS,
                                                 const float* __restrict__ MS,
                                                 const float* __restrict__ W,
                                                 const float* __restrict__ bias,
                                                 float* __restrict__ Y)
{
    __shared__ float Xs[CH*SP];
    __shared__ float Ws[CH*SP];
    __shared__ float as[NSPLIT][64];
    const int  tid  = threadIdx.x;
    const size_t base = (size_t)blockIdx.x * 64;

    if (tid < 64) {
        size_t r = base + tid;
        float m[NSPLIT], M = -1e30f;
#pragma unroll
        for (int s = 0; s < NSPLIT; s++) { m[s] = MS[(size_t)s*NROWS + r]; M = fmaxf(M, m[s]); }
        float num[NSPLIT], denom = 0.f;
#pragma unroll
        for (int s = 0; s < NSPLIT; s++) {
            num[s] = LS[(size_t)s*NROWS + r] * exp2f(m[s] - M);
            denom += num[s];
        }
        float inv = 1.f / denom;
#pragma unroll
        for (int s = 0; s < NSPLIT; s++) as[s][tid] = num[s]*inv;
    }
    __syncthreads();

#pragma unroll
    for (int rep = 0; rep < 4; rep++) {
        int idx = tid + rep*256;
        int r = idx >> 4, q = idx & 15;
        float x0 = 0.f, x1 = 0.f, x2 = 0.f, x3 = 0.f;
#pragma unroll
        for (int s = 0; s < NSPLIT; s++) {
            float a = as[s][r];
            uint2 hv = *(const uint2*)(OPh + (size_t)s*NROWS*32 + (base + r)*32 + q*2);
            float2 f0 = __half22float2(*reinterpret_cast<__half2*>(&hv.x));
            float2 f1 = __half22float2(*reinterpret_cast<__half2*>(&hv.y));
            x0 = fmaf(f0.x, a, x0);
            x1 = fmaf(f0.y, a, x1);
            x2 = fmaf(f1.x, a, x2);
            x3 = fmaf(f1.y, a, x3);
        }
        Xs[(q*4+0)*SP + r] = x0;
        Xs[(q*4+1)*SP + r] = x1;
        Xs[(q*4+2)*SP + r] = x2;
        Xs[(q*4+3)*SP + r] = x3;
        *(float4*)(Ws + r*SP + q*4) = *(const float4*)(W + idx*4);
    }
    __syncthreads();

    const int tx = tid & 15, ty = tid >> 4;
    const int i0 = ty*4,  c0 = tx*4;
    float acc[4][4] = {};

#pragma unroll 8
    for (int ci = 0; ci < CH; ci++) {
        float4 a4 = *(const float4*)(Xs + ci*SP + i0);
        float4 w4 = *(const float4*)(Ws + ci*SP + c0);
        float a[4] = {a4.x, a4.y, a4.z, a4.w};
        float w[4] = {w4.x, w4.y, w4.z, w4.w};
#pragma unroll
        for (int ii = 0; ii < 4; ii++)
#pragma unroll
            for (int jj = 0; jj < 4; jj++)
                acc[ii][jj] = fmaf(a[ii], w[jj], acc[ii][jj]);
    }

    float4 bv = *(const float4*)(bias + c0);
#pragma unroll
    for (int ii = 0; ii < 4; ii++) {
        float4 o;
        o.x = acc[ii][0] + bv.x;
        o.y = acc[ii][1] + bv.y;
        o.z = acc[ii][2] + bv.z;
        o.w = acc[ii][3] + bv.w;
        *(float4*)(Y + (base + i0 + ii)*CH + c0) = o;
    }
}

// ---------------------------------------------------------------------------
extern "C" void kernel_launch(void* const* d_in, const int* in_sizes, int n_in,
                              void* d_out, int out_size)
{
    const float* Q  = (const float*)d_in[0];
    const float* K  = (const float*)d_in[1];
    const float* V  = (const float*)d_in[2];
    const float* wq = (const float*)d_in[3];
    const float* bq = (const float*)d_in[4];
    const float* wk = (const float*)d_in[5];
    const float* bk = (const float*)d_in[6];
    const float* wv = (const float*)d_in[7];
    const float* bv = (const float*)d_in[8];
    const float* wd = (const float*)d_in[9];
    const float* bd = (const float*)d_in[10];
    const float* wo = (const float*)d_in[11];
    const float* bo = (const float*)d_in[12];
    float* out = (float*)d_out;

    float *ls, *ms, *bc, *c0v, *cLv;
    uint32_t *oph;
    uint4 *xi, *qi, *ki, *vi, *wb;
    cudaGetSymbolAddress((void**)&oph, g_oph);
    cudaGetSymbolAddress((void**)&ls,  g_ls);
    cudaGetSymbolAddress((void**)&ms,  g_ms);
    cudaGetSymbolAddress((void**)&bc,  g_bc);
    cudaGetSymbolAddress((void**)&c0v, g_c0);
    cudaGetSymbolAddress((void**)&cLv, g_cL);
    cudaGetSymbolAddress((void**)&xi,  g_xi);
    cudaGetSymbolAddress((void**)&qi,  g_qi);
    cudaGetSymbolAddress((void**)&ki,  g_ki);
    cudaGetSymbolAddress((void**)&vi,  g_vi);
    cudaGetSymbolAddress((void**)&wb,  g_wb);

    const dim3 gridCA(4, 3);
    const dim3 gridCV(SEQ/128, BATCH, 3);
    const dim3 gridFL(SEQ/64, BATCH, NSPLIT);
    const dim3 gridPW(NROWS/64);

    compose_all<<<gridCA, 256>>>(wq, wk, wv, wd, bq, bk, bv, bd,
                                 (uint32_t*)wb, bc, c0v, cLv);            // 0
    presplit<<<3*NROWS*16/256, 256>>>(Q, K, V, xi);                       // 1

    cudaFuncSetAttribute(conv3mma,
                         cudaFuncAttributeMaxDynamicSharedMemorySize, CV_SMEM);
    conv3mma<<<gridCV, 256, CV_SMEM>>>(xi, wb, bc, c0v, cLv,
                                       (uint32_t*)qi, (uint32_t*)ki,
                                       (uint32_t*)vi);                    // 2

    cudaFuncSetAttribute(flash_mma14,
                         cudaFuncAttributeMaxDynamicSharedMemorySize, FL_SMEM);
    flash_mma14<<<gridFL, 128, FL_SMEM>>>(qi, ki, vi, oph, ls, ms);       // 3

    pw_kernel<<<gridPW, 256>>>(oph, ls, ms, wo, bo, out);                 // 4
}